// round 2
// baseline (speedup 1.0000x reference)
#include <cuda_runtime.h>
#include <cuda_bf16.h>
#include <math.h>

// Problem constants
#define LAYERS 4
#define D 512
#define H 8
#define HD 64
#define FF 1024
#define B 64
#define S 64
#define M_TOT (B * S)          // 4096 rows
#define EPS 1e-5f

// ---------------------------------------------------------------------------
// Scratch buffers (device globals: no allocation allowed in kernel_launch)
// ---------------------------------------------------------------------------
__device__ float g_x[M_TOT * D];        // activations (8 MB)
__device__ float g_qkv[M_TOT * 3 * D];  // qkv (24 MB)
__device__ float g_ao[M_TOT * D];       // attention output (8 MB)
__device__ float g_tmp[M_TOT * D];      // attended / ff output (8 MB)
__device__ float g_h[M_TOT * FF];       // ff hidden (16 MB)
__device__ float g_f[M_TOT * FF];       // head f (16 MB)
__device__ float g_t[M_TOT * FF];       // head t (16 MB)

__device__ __forceinline__ float gelu_exact(float x) {
    return 0.5f * x * (1.0f + erff(x * 0.70710678118654752f));
}

// ---------------------------------------------------------------------------
// SGEMM-NT: C[m,n] = sum_k A[m*lda+k] * Bm[n*ldb+k] (+ bias[n]) (opt gelu)
// Tiles: BM=BN=128, BK=8; 256 threads; 8x8 micro-tile per thread.
// All M,N,K here are multiples of the tile sizes -> no bounds checks.
// ---------------------------------------------------------------------------
#define GBM 128
#define GBN 128
#define GBK 8

template <bool GELU>
__global__ void __launch_bounds__(256) sgemm_nt(
    const float* __restrict__ A, int lda,
    const float* __restrict__ Bm, int ldb,
    const float* __restrict__ bias,
    float* __restrict__ C, int ldc, int K)
{
    __shared__ __align__(16) float As[GBK][GBM];
    __shared__ __align__(16) float Bs[GBK][GBN];

    const int tid = threadIdx.x;
    const int brow = blockIdx.y * GBM;
    const int bcol = blockIdx.x * GBN;

    // Loader mapping: each thread loads one float4 of A and one of B per k-tile
    const int lr = tid >> 1;            // 0..127 (tile row)
    const int lk = (tid & 1) * 4;       // 0 or 4 (k offset)
    const float* Aptr = A + (size_t)(brow + lr) * lda + lk;
    const float* Bptr = Bm + (size_t)(bcol + lr) * ldb + lk;

    // Compute mapping: 16x16 threads, each owns 8x8 outputs
    const int tr = (tid >> 4) * 8;
    const int tc = (tid & 15) * 8;

    float acc[8][8];
#pragma unroll
    for (int i = 0; i < 8; i++)
#pragma unroll
        for (int j = 0; j < 8; j++) acc[i][j] = 0.0f;

    for (int k0 = 0; k0 < K; k0 += GBK) {
        float4 av = *(const float4*)(Aptr + k0);
        float4 bv = *(const float4*)(Bptr + k0);
        As[lk + 0][lr] = av.x; As[lk + 1][lr] = av.y;
        As[lk + 2][lr] = av.z; As[lk + 3][lr] = av.w;
        Bs[lk + 0][lr] = bv.x; Bs[lk + 1][lr] = bv.y;
        Bs[lk + 2][lr] = bv.z; Bs[lk + 3][lr] = bv.w;
        __syncthreads();

#pragma unroll
        for (int kk = 0; kk < GBK; kk++) {
            float a[8], bb[8];
            *(float4*)(a)     = *(const float4*)(&As[kk][tr]);
            *(float4*)(a + 4) = *(const float4*)(&As[kk][tr + 4]);
            *(float4*)(bb)     = *(const float4*)(&Bs[kk][tc]);
            *(float4*)(bb + 4) = *(const float4*)(&Bs[kk][tc + 4]);
#pragma unroll
            for (int i = 0; i < 8; i++)
#pragma unroll
                for (int j = 0; j < 8; j++)
                    acc[i][j] = fmaf(a[i], bb[j], acc[i][j]);
        }
        __syncthreads();
    }

    // Epilogue
    float bv[8];
#pragma unroll
    for (int j = 0; j < 8; j++) bv[j] = bias ? bias[bcol + tc + j] : 0.0f;

#pragma unroll
    for (int i = 0; i < 8; i++) {
        float out[8];
#pragma unroll
        for (int j = 0; j < 8; j++) {
            float v = acc[i][j] + bv[j];
            if (GELU) v = gelu_exact(v);
            out[j] = v;
        }
        float* crow = C + (size_t)(brow + tr + i) * ldc + bcol + tc;
        *(float4*)(crow)     = *(const float4*)(out);
        *(float4*)(crow + 4) = *(const float4*)(out + 4);
    }
}

// ---------------------------------------------------------------------------
// Attention: one block per (b,h). S=64, HD=64 -> everything fits in smem.
// ---------------------------------------------------------------------------
__global__ void __launch_bounds__(256) attn_kernel(
    const float* __restrict__ qkv, float* __restrict__ out)
{
    const int bh = blockIdx.x;
    const int b = bh >> 3;
    const int h = bh & 7;

    __shared__ __align__(16) float Qs[64][64];   // reused as P after scores
    __shared__ __align__(16) float Kt[64][64];   // Kt[d][j] (transposed)
    __shared__ __align__(16) float Vs[64][64];

    const int tid = threadIdx.x;
    const float* base = qkv + (size_t)b * S * (3 * D) + h * HD;

    // Load Q,K,V: each thread handles one row-quarter (16 elems = 4x float4)
    const int r = tid >> 2;
    const int c0 = (tid & 3) * 16;
#pragma unroll
    for (int i = 0; i < 4; i++) {
        int c = c0 + i * 4;
        float4 qv = *(const float4*)(base + (size_t)r * (3 * D) + c);
        float4 kv = *(const float4*)(base + (size_t)r * (3 * D) + D + c);
        float4 vv = *(const float4*)(base + (size_t)r * (3 * D) + 2 * D + c);
        *(float4*)(&Qs[r][c]) = qv;
        *(float4*)(&Vs[r][c]) = vv;
        Kt[c + 0][r] = kv.x; Kt[c + 1][r] = kv.y;
        Kt[c + 2][r] = kv.z; Kt[c + 3][r] = kv.w;
    }
    __syncthreads();

    // Scores into registers (16 per thread)
    float sc[16];
#pragma unroll
    for (int k = 0; k < 16; k++) {
        int idx = tid + k * 256;
        int i = idx >> 6, j = idx & 63;
        float s = 0.0f;
#pragma unroll
        for (int d = 0; d < 64; d++) s = fmaf(Qs[i][d], Kt[d][j], s);
        sc[k] = s * 0.125f;   // 1/sqrt(64)
    }
    __syncthreads();

    float (*P)[64] = Qs;   // overlay
#pragma unroll
    for (int k = 0; k < 16; k++) {
        int idx = tid + k * 256;
        P[idx >> 6][idx & 63] = sc[k];
    }
    __syncthreads();

    // Softmax: 8 warps, each handles 8 rows
    const int warp = tid >> 5, lane = tid & 31;
#pragma unroll
    for (int rr = 0; rr < 8; rr++) {
        int i = warp + rr * 8;
        float v0 = P[i][lane], v1 = P[i][lane + 32];
        float m = fmaxf(v0, v1);
#pragma unroll
        for (int o = 16; o > 0; o >>= 1) m = fmaxf(m, __shfl_xor_sync(~0u, m, o));
        float e0 = __expf(v0 - m), e1 = __expf(v1 - m);
        float s = e0 + e1;
#pragma unroll
        for (int o = 16; o > 0; o >>= 1) s += __shfl_xor_sync(~0u, s, o);
        float inv = 1.0f / s;
        P[i][lane] = e0 * inv;
        P[i][lane + 32] = e1 * inv;
    }
    __syncthreads();

    // O = P @ V, write back in (B,S,D) layout
#pragma unroll
    for (int k = 0; k < 16; k++) {
        int idx = tid + k * 256;
        int i = idx >> 6, d = idx & 63;
        float o = 0.0f;
#pragma unroll
        for (int j = 0; j < 64; j++) o = fmaf(P[i][j], Vs[j][d], o);
        out[(size_t)(b * S + i) * D + h * HD + d] = o;
    }
}

// ---------------------------------------------------------------------------
// Fused residual add + LayerNorm: x = LN(x + y) rowwise over D=512
// One block (128 threads) per row.
// ---------------------------------------------------------------------------
__global__ void __launch_bounds__(128) add_ln_kernel(
    float* __restrict__ x, const float* __restrict__ y,
    const float* __restrict__ g, const float* __restrict__ bta)
{
    const int row = blockIdx.x;
    const int tid = threadIdx.x;
    const int warp = tid >> 5, lane = tid & 31;

    float4 xv = *(const float4*)(x + (size_t)row * D + tid * 4);
    float4 yv = *(const float4*)(y + (size_t)row * D + tid * 4);
    float s0 = xv.x + yv.x, s1 = xv.y + yv.y, s2 = xv.z + yv.z, s3 = xv.w + yv.w;

    float sum = s0 + s1 + s2 + s3;
    float sq = fmaf(s0, s0, fmaf(s1, s1, fmaf(s2, s2, s3 * s3)));
#pragma unroll
    for (int o = 16; o > 0; o >>= 1) {
        sum += __shfl_xor_sync(~0u, sum, o);
        sq  += __shfl_xor_sync(~0u, sq, o);
    }
    __shared__ float sh[8];
    if (lane == 0) { sh[warp] = sum; sh[4 + warp] = sq; }
    __syncthreads();
    sum = sh[0] + sh[1] + sh[2] + sh[3];
    sq  = sh[4] + sh[5] + sh[6] + sh[7];

    const float mu = sum * (1.0f / D);
    const float var = sq * (1.0f / D) - mu * mu;
    const float inv = rsqrtf(var + EPS);

    float4 gv = *(const float4*)(g + tid * 4);
    float4 bv = *(const float4*)(bta + tid * 4);
    float4 outv;
    outv.x = (s0 - mu) * inv * gv.x + bv.x;
    outv.y = (s1 - mu) * inv * gv.y + bv.y;
    outv.z = (s2 - mu) * inv * gv.z + bv.z;
    outv.w = (s3 - mu) * inv * gv.w + bv.w;
    *(float4*)(x + (size_t)row * D + tid * 4) = outv;
}

// ---------------------------------------------------------------------------
// Pairwise policy head:
// out[b, f*64 + t] = sum_h gelu(F[b,f,h] + T[b,t,h] + bm1[h]) * wm2[h] + bm2
// Block: (b, f-tile of 8) -> 512 blocks, 256 threads, 2 (f,t) pairs/thread.
// ---------------------------------------------------------------------------
#define PCH 128

__global__ void __launch_bounds__(256) pairwise_kernel(
    const float* __restrict__ F, const float* __restrict__ T,
    const float* __restrict__ bm1, const float* __restrict__ wm2,
    const float* __restrict__ bm2v, float* __restrict__ out)
{
    const int b = blockIdx.x >> 3;
    const int ft = blockIdx.x & 7;

    __shared__ float Fs[8][PCH + 1];
    __shared__ float Ts[64][PCH + 1];
    __shared__ __align__(16) float ws[PCH];

    const int tid = threadIdx.x;
    const int f = tid & 7;
    const int t0 = (tid >> 3) * 2;

    float acc0 = 0.0f, acc1 = 0.0f;
    const float* Fbase = F + ((size_t)b * S + ft * 8) * FF;
    const float* Tbase = T + (size_t)b * S * FF;

    for (int c = 0; c < FF; c += PCH) {
        // F tile: 8 x 128 -> 256 float4 (one per thread)
        {
            int fr = tid >> 5, cc = (tid & 31) * 4;
            float4 fv = *(const float4*)(Fbase + (size_t)fr * FF + c + cc);
            Fs[fr][cc + 0] = fv.x; Fs[fr][cc + 1] = fv.y;
            Fs[fr][cc + 2] = fv.z; Fs[fr][cc + 3] = fv.w;
        }
        // weights
        if (tid < 32) *(float4*)(&ws[tid * 4]) = *(const float4*)(wm2 + c + tid * 4);
        // T tile: 64 x 128 (+bm1 folded in) -> 8 float4 per thread
        {
            int tr = tid >> 2, tcc0 = (tid & 3) * 32;
#pragma unroll
            for (int i = 0; i < 8; i++) {
                int cc = tcc0 + i * 4;
                float4 tv = *(const float4*)(Tbase + (size_t)tr * FF + c + cc);
                float4 bb = *(const float4*)(bm1 + c + cc);
                Ts[tr][cc + 0] = tv.x + bb.x;
                Ts[tr][cc + 1] = tv.y + bb.y;
                Ts[tr][cc + 2] = tv.z + bb.z;
                Ts[tr][cc + 3] = tv.w + bb.w;
            }
        }
        __syncthreads();

#pragma unroll 4
        for (int hh = 0; hh < PCH; hh++) {
            float fv = Fs[f][hh];
            float w = ws[hh];
            float a0 = fv + Ts[t0][hh];
            float a1 = fv + Ts[t0 + 1][hh];
            acc0 = fmaf(gelu_exact(a0), w, acc0);
            acc1 = fmaf(gelu_exact(a1), w, acc1);
        }
        __syncthreads();
    }

    const float bm2s = bm2v[0];
    const int fg = ft * 8 + f;
    float* orow = out + ((size_t)b * S + fg) * S;
    orow[t0]     = acc0 + bm2s;
    orow[t0 + 1] = acc1 + bm2s;
}

// ---------------------------------------------------------------------------
// Launcher
// ---------------------------------------------------------------------------
extern "C" void kernel_launch(void* const* d_in, const int* in_sizes, int n_in,
                              void* d_out, int out_size)
{
    const float* emb   = (const float*)d_in[0];
    const float* Wqkv  = (const float*)d_in[1];
    const float* bqkv  = (const float*)d_in[2];
    const float* Wo    = (const float*)d_in[3];
    const float* bo    = (const float*)d_in[4];
    const float* ln1_g = (const float*)d_in[5];
    const float* ln1_b = (const float*)d_in[6];
    const float* ln2_g = (const float*)d_in[7];
    const float* ln2_b = (const float*)d_in[8];
    const float* W1    = (const float*)d_in[9];
    const float* b1    = (const float*)d_in[10];
    const float* W2    = (const float*)d_in[11];
    const float* b2    = (const float*)d_in[12];
    const float* Wm1   = (const float*)d_in[13];
    const float* bm1   = (const float*)d_in[14];
    const float* Wm2   = (const float*)d_in[15];
    const float* bm2   = (const float*)d_in[16];
    float* out = (float*)d_out;

    float *x, *qkvb, *ao, *tmp, *hb, *fb, *tb;
    cudaGetSymbolAddress((void**)&x, g_x);
    cudaGetSymbolAddress((void**)&qkvb, g_qkv);
    cudaGetSymbolAddress((void**)&ao, g_ao);
    cudaGetSymbolAddress((void**)&tmp, g_tmp);
    cudaGetSymbolAddress((void**)&hb, g_h);
    cudaGetSymbolAddress((void**)&fb, g_f);
    cudaGetSymbolAddress((void**)&tb, g_t);

    cudaMemcpyAsync(x, emb, (size_t)M_TOT * D * sizeof(float),
                    cudaMemcpyDeviceToDevice);

    const dim3 gQKV(3 * D / GBN, M_TOT / GBM);   // (12, 32)
    const dim3 gD  (D / GBN,     M_TOT / GBM);   // (4, 32)
    const dim3 gFF (FF / GBN,    M_TOT / GBM);   // (8, 32)

    for (int l = 0; l < LAYERS; l++) {
        sgemm_nt<false><<<gQKV, 256>>>(x, D, Wqkv + (size_t)l * 3 * D * D, D,
                                       bqkv + (size_t)l * 3 * D, qkvb, 3 * D, D);
        attn_kernel<<<B * H, 256>>>(qkvb, ao);
        sgemm_nt<false><<<gD, 256>>>(ao, D, Wo + (size_t)l * D * D, D,
                                     bo + (size_t)l * D, tmp, D, D);
        add_ln_kernel<<<M_TOT, 128>>>(x, tmp, ln1_g + (size_t)l * D,
                                      ln1_b + (size_t)l * D);
        sgemm_nt<true><<<gFF, 256>>>(x, D, W1 + (size_t)l * FF * D, D,
                                     b1 + (size_t)l * FF, hb, FF, D);
        sgemm_nt<false><<<gD, 256>>>(hb, FF, W2 + (size_t)l * D * FF, FF,
                                     b2 + (size_t)l * D, tmp, D, FF);
        add_ln_kernel<<<M_TOT, 128>>>(x, tmp, ln2_g + (size_t)l * D,
                                      ln2_b + (size_t)l * D);
    }

    // Policy head: f = x @ Wm1[:, :D]^T, t = x @ Wm1[:, D:]^T
    sgemm_nt<false><<<gFF, 256>>>(x, D, Wm1, 2 * D, nullptr, fb, FF, D);
    sgemm_nt<false><<<gFF, 256>>>(x, D, Wm1 + D, 2 * D, nullptr, tb, FF, D);
    pairwise_kernel<<<B * 8, 256>>>(fb, tb, bm1, Wm2, bm2, out);
}

// round 4
// speedup vs baseline: 2.1705x; 2.1705x over previous
#include <cuda_runtime.h>
#include <cuda_bf16.h>
#include <math.h>
#include <stdint.h>

// Problem constants
#define LAYERS 4
#define D 512
#define H 8
#define HD 64
#define FF 1024
#define B 64
#define S 64
#define M_TOT (B * S)
#define EPS 1e-5f

// ---------------------------------------------------------------------------
// Scratch buffers
// ---------------------------------------------------------------------------
__device__ float g_x[M_TOT * D];
__device__ float g_qkv[M_TOT * 3 * D];
__device__ float g_ao[M_TOT * D];
__device__ float g_tmp[M_TOT * D];
__device__ float g_f[M_TOT * FF];
__device__ float g_t[M_TOT * FF];

__device__ __nv_bfloat16 g_xh[M_TOT * D],  g_xl[M_TOT * D];
__device__ __nv_bfloat16 g_aoh[M_TOT * D], g_aol[M_TOT * D];
__device__ __nv_bfloat16 g_hh[M_TOT * FF], g_hl[M_TOT * FF];
__device__ __nv_bfloat16 g_wqkvh[LAYERS * 3 * D * D], g_wqkvl[LAYERS * 3 * D * D];
__device__ __nv_bfloat16 g_woh[LAYERS * D * D],       g_wol[LAYERS * D * D];
__device__ __nv_bfloat16 g_w1h[LAYERS * FF * D],      g_w1l[LAYERS * FF * D];
__device__ __nv_bfloat16 g_w2h[LAYERS * D * FF],      g_w2l[LAYERS * D * FF];
__device__ __nv_bfloat16 g_wm1h[FF * 2 * D],          g_wm1l[FF * 2 * D];

__device__ __forceinline__ float gelu_exact(float x) {
    return 0.5f * x * (1.0f + erff(x * 0.70710678118654752f));
}

__device__ __forceinline__ uint32_t smem_u32(const void* p) {
    uint32_t a;
    asm("{ .reg .u64 t; cvta.to.shared.u64 t, %1; cvt.u32.u64 %0, t; }"
        : "=r"(a) : "l"(p));
    return a;
}

__device__ __forceinline__ void ldmx4(uint32_t* r, uint32_t addr) {
    asm volatile("ldmatrix.sync.aligned.m8n8.x4.shared.b16 {%0,%1,%2,%3}, [%4];"
                 : "=r"(r[0]), "=r"(r[1]), "=r"(r[2]), "=r"(r[3]) : "r"(addr));
}

__device__ __forceinline__ void mma16816(float* d, const uint32_t* a,
                                         const uint32_t* b) {
    asm volatile(
        "mma.sync.aligned.m16n8k16.row.col.f32.bf16.bf16.f32 "
        "{%0,%1,%2,%3}, {%4,%5,%6,%7}, {%8,%9}, {%0,%1,%2,%3};"
        : "+f"(d[0]), "+f"(d[1]), "+f"(d[2]), "+f"(d[3])
        : "r"(a[0]), "r"(a[1]), "r"(a[2]), "r"(a[3]), "r"(b[0]), "r"(b[1]));
}

__device__ __forceinline__ void cp16(uint32_t saddr, const void* gptr) {
    asm volatile("cp.async.cg.shared.global [%0], [%1], 16;"
                 :: "r"(saddr), "l"(gptr));
}
__device__ __forceinline__ void cp_commit() {
    asm volatile("cp.async.commit_group;");
}
template <int N>
__device__ __forceinline__ void cp_wait() {
    asm volatile("cp.async.wait_group %0;" :: "n"(N));
}

// ---------------------------------------------------------------------------
// f32 -> (hi, lo) bf16 split converter. n multiple of 1024.
// ---------------------------------------------------------------------------
__global__ void __launch_bounds__(256) conv_pair(
    const float4* __restrict__ in, __nv_bfloat162* __restrict__ hi,
    __nv_bfloat162* __restrict__ lo)
{
    int idx = blockIdx.x * 256 + threadIdx.x;
    float4 v = in[idx];
    __nv_bfloat16 hx = __float2bfloat16_rn(v.x);
    __nv_bfloat16 hy = __float2bfloat16_rn(v.y);
    __nv_bfloat16 hz = __float2bfloat16_rn(v.z);
    __nv_bfloat16 hw = __float2bfloat16_rn(v.w);
    __nv_bfloat162 h0; h0.x = hx; h0.y = hy;
    __nv_bfloat162 h1; h1.x = hz; h1.y = hw;
    __nv_bfloat162 l0, l1;
    l0.x = __float2bfloat16_rn(v.x - __bfloat162float(hx));
    l0.y = __float2bfloat16_rn(v.y - __bfloat162float(hy));
    l1.x = __float2bfloat16_rn(v.z - __bfloat162float(hz));
    l1.y = __float2bfloat16_rn(v.w - __bfloat162float(hw));
    hi[idx * 2] = h0; hi[idx * 2 + 1] = h1;
    lo[idx * 2] = l0; lo[idx * 2 + 1] = l1;
}

// ---------------------------------------------------------------------------
// Split-bf16 tensor-core GEMM via mma.sync (HMMA):
//   C[m,n] = sum_k A[m,k]*B[n,k] (+bias) (MODE1: gelu -> bf16 hi/lo out)
// 128x128 block, 8 warps (2x4), 64x32 per warp, K chunks of 32,
// 2-stage cp.async pipeline.
// ---------------------------------------------------------------------------
#define AROW 80                         // padded row stride bytes (32 bf16 -> 64B data)
#define TILE_B (128 * AROW)             // 10240
#define ST_AH 0
#define ST_AL TILE_B
#define ST_BH (2 * TILE_B)
#define ST_BL (3 * TILE_B)
#define STAGE_B (4 * TILE_B)            // 40960
#define TC_SMEM (2 * STAGE_B)           // 81920

template <int MODE>
__global__ void __launch_bounds__(256) tc_gemm(
    const __nv_bfloat16* __restrict__ Ah, const __nv_bfloat16* __restrict__ Al, int lda,
    const __nv_bfloat16* __restrict__ Bh, const __nv_bfloat16* __restrict__ Bl, int ldb,
    const float* __restrict__ bias,
    float* __restrict__ C, __nv_bfloat16* __restrict__ Ch, __nv_bfloat16* __restrict__ Cl,
    int ldc, int K)
{
    extern __shared__ char smem[];
    const uint32_t sb = smem_u32(smem);
    const int tid = threadIdx.x;
    const int wid = tid >> 5, lane = tid & 31;
    const int wm = wid >> 2;            // 0..1
    const int wn = wid & 3;             // 0..3
    const int brow = blockIdx.y * 128;
    const int bcol = blockIdx.x * 128;

    // global load mapping: 2 segs per thread per tile
    int rowg[2], segb[2], smoff[2];
#pragma unroll
    for (int t = 0; t < 2; t++) {
        int sid = tid + (t << 8);
        rowg[t] = sid >> 2;
        segb[t] = (sid & 3) * 8;        // elems
        smoff[t] = rowg[t] * AROW + (sid & 3) * 16;
    }
    const __nv_bfloat16* pAh = Ah + (size_t)brow * lda;
    const __nv_bfloat16* pAl = Al + (size_t)brow * lda;
    const __nv_bfloat16* pBh = Bh + (size_t)bcol * ldb;
    const __nv_bfloat16* pBl = Bl + (size_t)bcol * ldb;

    // ldmatrix lane offsets
    const uint32_t a_loff = (uint32_t)((wm * 64 + (lane & 15)) * AROW + (lane >> 4) * 16);
    const uint32_t b_loff = (uint32_t)((wn * 32 + (lane & 7) + ((lane >> 4) << 3)) * AROW
                                       + ((lane >> 3) & 1) * 16);

    float acc[4][4][4];
#pragma unroll
    for (int i = 0; i < 4; i++)
#pragma unroll
        for (int j = 0; j < 4; j++)
#pragma unroll
            for (int e = 0; e < 4; e++) acc[i][j][e] = 0.0f;

    const int NC = K >> 5;              // chunks of 32

    // prefetch chunk 0 -> stage 0
    {
        const uint32_t s0 = sb;
#pragma unroll
        for (int t = 0; t < 2; t++) {
            int go = rowg[t] * lda + segb[t];
            int gob = rowg[t] * ldb + segb[t];
            cp16(s0 + ST_AH + smoff[t], pAh + go);
            cp16(s0 + ST_AL + smoff[t], pAl + go);
            cp16(s0 + ST_BH + smoff[t], pBh + gob);
            cp16(s0 + ST_BL + smoff[t], pBl + gob);
        }
        cp_commit();
    }

    for (int c = 0; c < NC; c++) {
        if (c + 1 < NC) {
            const uint32_t sn = sb + ((c + 1) & 1) * STAGE_B;
            const int kc = (c + 1) << 5;
#pragma unroll
            for (int t = 0; t < 2; t++) {
                int go = rowg[t] * lda + segb[t] + kc;
                int gob = rowg[t] * ldb + segb[t] + kc;
                cp16(sn + ST_AH + smoff[t], pAh + go);
                cp16(sn + ST_AL + smoff[t], pAl + go);
                cp16(sn + ST_BH + smoff[t], pBh + gob);
                cp16(sn + ST_BL + smoff[t], pBl + gob);
            }
            cp_commit();
            cp_wait<1>();
        } else {
            cp_wait<0>();
        }
        __syncthreads();

        const uint32_t base = sb + (c & 1) * STAGE_B;
#pragma unroll
        for (int kk = 0; kk < 2; kk++) {
            const uint32_t kb = kk * 32;    // 16 elems * 2B
            uint32_t bh[8], bl[8];
#pragma unroll
            for (int j = 0; j < 2; j++) {
                ldmx4(&bh[j * 4], base + ST_BH + j * (16 * AROW) + kb + b_loff);
                ldmx4(&bl[j * 4], base + ST_BL + j * (16 * AROW) + kb + b_loff);
            }
#pragma unroll
            for (int i = 0; i < 4; i++) {
                uint32_t ah[4], al[4];
                ldmx4(ah, base + ST_AH + i * (16 * AROW) + kb + a_loff);
                ldmx4(al, base + ST_AL + i * (16 * AROW) + kb + a_loff);
#pragma unroll
                for (int jn = 0; jn < 4; jn++) {
                    const uint32_t* bhp = &bh[(jn >> 1) * 4 + (jn & 1) * 2];
                    const uint32_t* blp = &bl[(jn >> 1) * 4 + (jn & 1) * 2];
                    mma16816(acc[i][jn], ah, bhp);
                    mma16816(acc[i][jn], ah, blp);
                    mma16816(acc[i][jn], al, bhp);
                }
            }
        }
        __syncthreads();
    }

    // Epilogue
    const int lm = lane >> 2;
    const int ln = (lane & 3) * 2;
#pragma unroll
    for (int i = 0; i < 4; i++) {
#pragma unroll
        for (int jn = 0; jn < 4; jn++) {
            const int r0 = brow + wm * 64 + i * 16 + lm;
            const int n = bcol + wn * 32 + jn * 8 + ln;
            float b0 = bias ? bias[n] : 0.0f;
            float b1 = bias ? bias[n + 1] : 0.0f;
            float d0 = acc[i][jn][0] + b0, d1 = acc[i][jn][1] + b1;
            float d2 = acc[i][jn][2] + b0, d3 = acc[i][jn][3] + b1;
            if (MODE == 0) {
                float2 o0 = make_float2(d0, d1);
                float2 o1 = make_float2(d2, d3);
                *(float2*)(C + (size_t)r0 * ldc + n) = o0;
                *(float2*)(C + (size_t)(r0 + 8) * ldc + n) = o1;
            } else {
                float a0 = gelu_exact(d0), a1 = gelu_exact(d1);
                float a2 = gelu_exact(d2), a3 = gelu_exact(d3);
                __nv_bfloat16 h0 = __float2bfloat16_rn(a0);
                __nv_bfloat16 h1 = __float2bfloat16_rn(a1);
                __nv_bfloat16 h2 = __float2bfloat16_rn(a2);
                __nv_bfloat16 h3 = __float2bfloat16_rn(a3);
                __nv_bfloat162 hp0; hp0.x = h0; hp0.y = h1;
                __nv_bfloat162 hp1; hp1.x = h2; hp1.y = h3;
                __nv_bfloat162 lp0, lp1;
                lp0.x = __float2bfloat16_rn(a0 - __bfloat162float(h0));
                lp0.y = __float2bfloat16_rn(a1 - __bfloat162float(h1));
                lp1.x = __float2bfloat16_rn(a2 - __bfloat162float(h2));
                lp1.y = __float2bfloat16_rn(a3 - __bfloat162float(h3));
                *(__nv_bfloat162*)(Ch + (size_t)r0 * ldc + n) = hp0;
                *(__nv_bfloat162*)(Cl + (size_t)r0 * ldc + n) = lp0;
                *(__nv_bfloat162*)(Ch + (size_t)(r0 + 8) * ldc + n) = hp1;
                *(__nv_bfloat162*)(Cl + (size_t)(r0 + 8) * ldc + n) = lp1;
            }
        }
    }
}

// ---------------------------------------------------------------------------
// Attention: one block per (b,h). S=64, HD=64 in smem.
// ---------------------------------------------------------------------------
__global__ void __launch_bounds__(256) attn_kernel(
    const float* __restrict__ qkv, float* __restrict__ out)
{
    const int bh = blockIdx.x;
    const int b = bh >> 3;
    const int h = bh & 7;

    __shared__ __align__(16) float Qs[64][64];
    __shared__ __align__(16) float Kt[64][64];
    __shared__ __align__(16) float Vs[64][64];

    const int tid = threadIdx.x;
    const float* base = qkv + (size_t)b * S * (3 * D) + h * HD;

    const int r = tid >> 2;
    const int c0 = (tid & 3) * 16;
#pragma unroll
    for (int i = 0; i < 4; i++) {
        int c = c0 + i * 4;
        float4 qv = *(const float4*)(base + (size_t)r * (3 * D) + c);
        float4 kv = *(const float4*)(base + (size_t)r * (3 * D) + D + c);
        float4 vv = *(const float4*)(base + (size_t)r * (3 * D) + 2 * D + c);
        *(float4*)(&Qs[r][c]) = qv;
        *(float4*)(&Vs[r][c]) = vv;
        Kt[c + 0][r] = kv.x; Kt[c + 1][r] = kv.y;
        Kt[c + 2][r] = kv.z; Kt[c + 3][r] = kv.w;
    }
    __syncthreads();

    float sc[16];
#pragma unroll
    for (int k = 0; k < 16; k++) {
        int idx = tid + k * 256;
        int i = idx >> 6, j = idx & 63;
        float s = 0.0f;
#pragma unroll
        for (int d = 0; d < 64; d++) s = fmaf(Qs[i][d], Kt[d][j], s);
        sc[k] = s * 0.125f;
    }
    __syncthreads();

    float (*P)[64] = Qs;
#pragma unroll
    for (int k = 0; k < 16; k++) {
        int idx = tid + k * 256;
        P[idx >> 6][idx & 63] = sc[k];
    }
    __syncthreads();

    const int warp = tid >> 5, lane = tid & 31;
#pragma unroll
    for (int rr = 0; rr < 8; rr++) {
        int i = warp + rr * 8;
        float v0 = P[i][lane], v1 = P[i][lane + 32];
        float mx = fmaxf(v0, v1);
#pragma unroll
        for (int o = 16; o > 0; o >>= 1) mx = fmaxf(mx, __shfl_xor_sync(~0u, mx, o));
        float e0 = __expf(v0 - mx), e1 = __expf(v1 - mx);
        float s = e0 + e1;
#pragma unroll
        for (int o = 16; o > 0; o >>= 1) s += __shfl_xor_sync(~0u, s, o);
        float inv = 1.0f / s;
        P[i][lane] = e0 * inv;
        P[i][lane + 32] = e1 * inv;
    }
    __syncthreads();

#pragma unroll
    for (int k = 0; k < 16; k++) {
        int idx = tid + k * 256;
        int i = idx >> 6, d = idx & 63;
        float o = 0.0f;
#pragma unroll
        for (int j = 0; j < 64; j++) o = fmaf(P[i][j], Vs[j][d], o);
        out[(size_t)(b * S + i) * D + h * HD + d] = o;
    }
}

// ---------------------------------------------------------------------------
// Fused residual add + LayerNorm + bf16 split emit
// ---------------------------------------------------------------------------
__global__ void __launch_bounds__(128) add_ln_kernel(
    float* __restrict__ x, const float* __restrict__ y,
    const float* __restrict__ g, const float* __restrict__ bta,
    __nv_bfloat16* __restrict__ xh, __nv_bfloat16* __restrict__ xl)
{
    const int row = blockIdx.x;
    const int tid = threadIdx.x;
    const int warp = tid >> 5, lane = tid & 31;

    float4 xv = *(const float4*)(x + (size_t)row * D + tid * 4);
    float4 yv = *(const float4*)(y + (size_t)row * D + tid * 4);
    float s0 = xv.x + yv.x, s1 = xv.y + yv.y, s2 = xv.z + yv.z, s3 = xv.w + yv.w;

    float sum = s0 + s1 + s2 + s3;
    float sq = fmaf(s0, s0, fmaf(s1, s1, fmaf(s2, s2, s3 * s3)));
#pragma unroll
    for (int o = 16; o > 0; o >>= 1) {
        sum += __shfl_xor_sync(~0u, sum, o);
        sq  += __shfl_xor_sync(~0u, sq, o);
    }
    __shared__ float sh[8];
    if (lane == 0) { sh[warp] = sum; sh[4 + warp] = sq; }
    __syncthreads();
    sum = sh[0] + sh[1] + sh[2] + sh[3];
    sq  = sh[4] + sh[5] + sh[6] + sh[7];

    const float mu = sum * (1.0f / D);
    const float var = sq * (1.0f / D) - mu * mu;
    const float inv = rsqrtf(var + EPS);

    float4 gv = *(const float4*)(g + tid * 4);
    float4 bv = *(const float4*)(bta + tid * 4);
    float o0 = (s0 - mu) * inv * gv.x + bv.x;
    float o1 = (s1 - mu) * inv * gv.y + bv.y;
    float o2 = (s2 - mu) * inv * gv.z + bv.z;
    float o3 = (s3 - mu) * inv * gv.w + bv.w;
    *(float4*)(x + (size_t)row * D + tid * 4) = make_float4(o0, o1, o2, o3);

    __nv_bfloat16 h0 = __float2bfloat16_rn(o0), h1 = __float2bfloat16_rn(o1);
    __nv_bfloat16 h2 = __float2bfloat16_rn(o2), h3 = __float2bfloat16_rn(o3);
    __nv_bfloat162 hp0; hp0.x = h0; hp0.y = h1;
    __nv_bfloat162 hp1; hp1.x = h2; hp1.y = h3;
    __nv_bfloat162 lp0, lp1;
    lp0.x = __float2bfloat16_rn(o0 - __bfloat162float(h0));
    lp0.y = __float2bfloat16_rn(o1 - __bfloat162float(h1));
    lp1.x = __float2bfloat16_rn(o2 - __bfloat162float(h2));
    lp1.y = __float2bfloat16_rn(o3 - __bfloat162float(h3));
    __nv_bfloat162* hq = (__nv_bfloat162*)(xh + (size_t)row * D);
    __nv_bfloat162* lq = (__nv_bfloat162*)(xl + (size_t)row * D);
    hq[tid * 2] = hp0; hq[tid * 2 + 1] = hp1;
    lq[tid * 2] = lp0; lq[tid * 2 + 1] = lp1;
}

// ---------------------------------------------------------------------------
// Pairwise policy head
// ---------------------------------------------------------------------------
#define PCH 128

__global__ void __launch_bounds__(256) pairwise_kernel(
    const float* __restrict__ F, const float* __restrict__ T,
    const float* __restrict__ bm1, const float* __restrict__ wm2,
    const float* __restrict__ bm2v, float* __restrict__ out)
{
    const int b = blockIdx.x >> 3;
    const int ft = blockIdx.x & 7;

    __shared__ float Fs[8][PCH + 1];
    __shared__ float Ts[64][PCH + 1];
    __shared__ __align__(16) float ws[PCH];

    const int tid = threadIdx.x;
    const int f = tid & 7;
    const int t0 = (tid >> 3) * 2;

    float acc0 = 0.0f, acc1 = 0.0f;
    const float* Fbase = F + ((size_t)b * S + ft * 8) * FF;
    const float* Tbase = T + (size_t)b * S * FF;

    for (int c = 0; c < FF; c += PCH) {
        {
            int fr = tid >> 5, cc = (tid & 31) * 4;
            float4 fv = *(const float4*)(Fbase + (size_t)fr * FF + c + cc);
            Fs[fr][cc + 0] = fv.x; Fs[fr][cc + 1] = fv.y;
            Fs[fr][cc + 2] = fv.z; Fs[fr][cc + 3] = fv.w;
        }
        if (tid < 32) *(float4*)(&ws[tid * 4]) = *(const float4*)(wm2 + c + tid * 4);
        {
            int tr = tid >> 2, tcc0 = (tid & 3) * 32;
#pragma unroll
            for (int i = 0; i < 8; i++) {
                int cc = tcc0 + i * 4;
                float4 tv = *(const float4*)(Tbase + (size_t)tr * FF + c + cc);
                float4 bb = *(const float4*)(bm1 + c + cc);
                Ts[tr][cc + 0] = tv.x + bb.x;
                Ts[tr][cc + 1] = tv.y + bb.y;
                Ts[tr][cc + 2] = tv.z + bb.z;
                Ts[tr][cc + 3] = tv.w + bb.w;
            }
        }
        __syncthreads();

#pragma unroll 4
        for (int hh = 0; hh < PCH; hh++) {
            float fv = Fs[f][hh];
            float w = ws[hh];
            float a0 = fv + Ts[t0][hh];
            float a1 = fv + Ts[t0 + 1][hh];
            acc0 = fmaf(gelu_exact(a0), w, acc0);
            acc1 = fmaf(gelu_exact(a1), w, acc1);
        }
        __syncthreads();
    }

    const float bm2s = bm2v[0];
    const int fg = ft * 8 + f;
    float* orow = out + ((size_t)b * S + fg) * S;
    orow[t0]     = acc0 + bm2s;
    orow[t0 + 1] = acc1 + bm2s;
}

// ---------------------------------------------------------------------------
// Launcher
// ---------------------------------------------------------------------------
extern "C" void kernel_launch(void* const* d_in, const int* in_sizes, int n_in,
                              void* d_out, int out_size)
{
    const float* emb   = (const float*)d_in[0];
    const float* Wqkv  = (const float*)d_in[1];
    const float* bqkv  = (const float*)d_in[2];
    const float* Wo    = (const float*)d_in[3];
    const float* bo    = (const float*)d_in[4];
    const float* ln1_g = (const float*)d_in[5];
    const float* ln1_b = (const float*)d_in[6];
    const float* ln2_g = (const float*)d_in[7];
    const float* ln2_b = (const float*)d_in[8];
    const float* W1    = (const float*)d_in[9];
    const float* b1    = (const float*)d_in[10];
    const float* W2    = (const float*)d_in[11];
    const float* b2    = (const float*)d_in[12];
    const float* Wm1   = (const float*)d_in[13];
    const float* bm1   = (const float*)d_in[14];
    const float* Wm2   = (const float*)d_in[15];
    const float* bm2   = (const float*)d_in[16];
    float* out = (float*)d_out;

    float *x, *qkvb, *ao, *tmp, *fb, *tb;
    cudaGetSymbolAddress((void**)&x, g_x);
    cudaGetSymbolAddress((void**)&qkvb, g_qkv);
    cudaGetSymbolAddress((void**)&ao, g_ao);
    cudaGetSymbolAddress((void**)&tmp, g_tmp);
    cudaGetSymbolAddress((void**)&fb, g_f);
    cudaGetSymbolAddress((void**)&tb, g_t);

    __nv_bfloat16 *xh, *xl, *aoh, *aol, *hh, *hl;
    __nv_bfloat16 *wqkvh, *wqkvl, *woh, *wol, *w1h, *w1l, *w2h, *w2l, *wm1h, *wm1l;
    cudaGetSymbolAddress((void**)&xh, g_xh);     cudaGetSymbolAddress((void**)&xl, g_xl);
    cudaGetSymbolAddress((void**)&aoh, g_aoh);   cudaGetSymbolAddress((void**)&aol, g_aol);
    cudaGetSymbolAddress((void**)&hh, g_hh);     cudaGetSymbolAddress((void**)&hl, g_hl);
    cudaGetSymbolAddress((void**)&wqkvh, g_wqkvh); cudaGetSymbolAddress((void**)&wqkvl, g_wqkvl);
    cudaGetSymbolAddress((void**)&woh, g_woh);   cudaGetSymbolAddress((void**)&wol, g_wol);
    cudaGetSymbolAddress((void**)&w1h, g_w1h);   cudaGetSymbolAddress((void**)&w1l, g_w1l);
    cudaGetSymbolAddress((void**)&w2h, g_w2h);   cudaGetSymbolAddress((void**)&w2l, g_w2l);
    cudaGetSymbolAddress((void**)&wm1h, g_wm1h); cudaGetSymbolAddress((void**)&wm1l, g_wm1l);

    cudaFuncSetAttribute(tc_gemm<0>, cudaFuncAttributeMaxDynamicSharedMemorySize, TC_SMEM);
    cudaFuncSetAttribute(tc_gemm<1>, cudaFuncAttributeMaxDynamicSharedMemorySize, TC_SMEM);

    cudaMemcpyAsync(x, emb, (size_t)M_TOT * D * sizeof(float),
                    cudaMemcpyDeviceToDevice);

    conv_pair<<<(LAYERS * 3 * D * D) / 1024, 256>>>((const float4*)Wqkv,
        (__nv_bfloat162*)wqkvh, (__nv_bfloat162*)wqkvl);
    conv_pair<<<(LAYERS * D * D) / 1024, 256>>>((const float4*)Wo,
        (__nv_bfloat162*)woh, (__nv_bfloat162*)wol);
    conv_pair<<<(LAYERS * FF * D) / 1024, 256>>>((const float4*)W1,
        (__nv_bfloat162*)w1h, (__nv_bfloat162*)w1l);
    conv_pair<<<(LAYERS * D * FF) / 1024, 256>>>((const float4*)W2,
        (__nv_bfloat162*)w2h, (__nv_bfloat162*)w2l);
    conv_pair<<<(FF * 2 * D) / 1024, 256>>>((const float4*)Wm1,
        (__nv_bfloat162*)wm1h, (__nv_bfloat162*)wm1l);
    conv_pair<<<(M_TOT * D) / 1024, 256>>>((const float4*)emb,
        (__nv_bfloat162*)xh, (__nv_bfloat162*)xl);

    const dim3 gQKV(3 * D / 128, M_TOT / 128);
    const dim3 gD  (D / 128,     M_TOT / 128);
    const dim3 gFF (FF / 128,    M_TOT / 128);

    for (int l = 0; l < LAYERS; l++) {
        tc_gemm<0><<<gQKV, 256, TC_SMEM>>>(
            xh, xl, D, wqkvh + (size_t)l * 3 * D * D, wqkvl + (size_t)l * 3 * D * D, D,
            bqkv + (size_t)l * 3 * D, qkvb, nullptr, nullptr, 3 * D, D);
        attn_kernel<<<B * H, 256>>>(qkvb, ao);
        conv_pair<<<(M_TOT * D) / 1024, 256>>>((const float4*)ao,
            (__nv_bfloat162*)aoh, (__nv_bfloat162*)aol);
        tc_gemm<0><<<gD, 256, TC_SMEM>>>(
            aoh, aol, D, woh + (size_t)l * D * D, wol + (size_t)l * D * D, D,
            bo + (size_t)l * D, tmp, nullptr, nullptr, D, D);
        add_ln_kernel<<<M_TOT, 128>>>(x, tmp, ln1_g + (size_t)l * D,
                                      ln1_b + (size_t)l * D, xh, xl);
        tc_gemm<1><<<gFF, 256, TC_SMEM>>>(
            xh, xl, D, w1h + (size_t)l * FF * D, w1l + (size_t)l * FF * D, D,
            b1 + (size_t)l * FF, nullptr, hh, hl, FF, D);
        tc_gemm<0><<<gD, 256, TC_SMEM>>>(
            hh, hl, FF, w2h + (size_t)l * D * FF, w2l + (size_t)l * D * FF, FF,
            b2 + (size_t)l * D, tmp, nullptr, nullptr, D, FF);
        add_ln_kernel<<<M_TOT, 128>>>(x, tmp, ln2_g + (size_t)l * D,
                                      ln2_b + (size_t)l * D, xh, xl);
    }

    tc_gemm<0><<<gFF, 256, TC_SMEM>>>(
        xh, xl, D, wm1h, wm1l, 2 * D, nullptr, fb, nullptr, nullptr, FF, D);
    tc_gemm<0><<<gFF, 256, TC_SMEM>>>(
        xh, xl, D, wm1h + D, wm1l + D, 2 * D, nullptr, tb, nullptr, nullptr, FF, D);
    pairwise_kernel<<<B * 8, 256>>>(fb, tb, bm1, Wm2, bm2, out);
}

// round 5
// speedup vs baseline: 2.8399x; 1.3084x over previous
#include <cuda_runtime.h>
#include <cuda_bf16.h>
#include <math.h>
#include <stdint.h>

#define LAYERS 4
#define D 512
#define H 8
#define HD 64
#define FF 1024
#define B 64
#define S 64
#define M_TOT (B * S)
#define EPS 1e-5f

// ---------------------------------------------------------------------------
// Scratch buffers
// ---------------------------------------------------------------------------
__device__ float g_x[M_TOT * D];
__device__ float g_qkv[M_TOT * 3 * D];
__device__ float g_ao[M_TOT * D];
__device__ float g_tmp[M_TOT * D];
__device__ float g_h[M_TOT * FF];
__device__ float g_f[M_TOT * FF];
__device__ float g_t[M_TOT * FF];

// int8 two-level quantized operands
__device__ int8_t q_x1[M_TOT * D],  q_x2[M_TOT * D];
__device__ int8_t q_ao1[M_TOT * D], q_ao2[M_TOT * D];
__device__ int8_t q_h1[M_TOT * FF], q_h2[M_TOT * FF];
__device__ int8_t q_wqkv1[LAYERS * 3 * D * D], q_wqkv2[LAYERS * 3 * D * D];
__device__ int8_t q_wo1[LAYERS * D * D],       q_wo2[LAYERS * D * D];
__device__ int8_t q_w11[LAYERS * FF * D],      q_w12[LAYERS * FF * D];
__device__ int8_t q_w21[LAYERS * D * FF],      q_w22[LAYERS * D * FF];
__device__ int8_t q_wm1f1[FF * D], q_wm1f2[FF * D];
__device__ int8_t q_wm1t1[FF * D], q_wm1t2[FF * D];

// per-row scales
__device__ float s_x[M_TOT], s_ao[M_TOT], s_h[M_TOT];
__device__ float s_wqkv[LAYERS * 3 * D], s_wo[LAYERS * D];
__device__ float s_w1[LAYERS * FF], s_w2[LAYERS * D];
__device__ float s_wm1f[FF], s_wm1t[FF];

__device__ __forceinline__ float gelu_exact(float x) {
    return 0.5f * x * (1.0f + erff(x * 0.70710678118654752f));
}

__device__ __forceinline__ uint32_t smem_u32(const void* p) {
    uint32_t a;
    asm("{ .reg .u64 t; cvta.to.shared.u64 t, %1; cvt.u32.u64 %0, t; }"
        : "=r"(a) : "l"(p));
    return a;
}

__device__ __forceinline__ void ldmx4(uint32_t* r, uint32_t addr) {
    asm volatile("ldmatrix.sync.aligned.m8n8.x4.shared.b16 {%0,%1,%2,%3}, [%4];"
                 : "=r"(r[0]), "=r"(r[1]), "=r"(r[2]), "=r"(r[3]) : "r"(addr));
}

__device__ __forceinline__ void imma(int* d, const uint32_t* a, const uint32_t* b) {
    asm volatile(
        "mma.sync.aligned.m16n8k32.row.col.s32.s8.s8.s32 "
        "{%0,%1,%2,%3}, {%4,%5,%6,%7}, {%8,%9}, {%0,%1,%2,%3};"
        : "+r"(d[0]), "+r"(d[1]), "+r"(d[2]), "+r"(d[3])
        : "r"(a[0]), "r"(a[1]), "r"(a[2]), "r"(a[3]), "r"(b[0]), "r"(b[1]));
}

__device__ __forceinline__ void cp16(uint32_t saddr, const void* gptr) {
    asm volatile("cp.async.cg.shared.global [%0], [%1], 16;"
                 :: "r"(saddr), "l"(gptr));
}
__device__ __forceinline__ void cp_commit() {
    asm volatile("cp.async.commit_group;");
}
template <int N>
__device__ __forceinline__ void cp_wait() {
    asm volatile("cp.async.wait_group %0;" :: "n"(N));
}

// ---------------------------------------------------------------------------
// Row-wise two-level int8 quantization: x ~ s*(q1 + q2/254), s = rowmax/127.
// One block (128 threads) per row. Row length = 128*NPT.
// ---------------------------------------------------------------------------
template <int NPT>   // 4 or 8 elems/thread
__global__ void __launch_bounds__(128) quant_rows(
    const float* __restrict__ src, int lds,
    int8_t* __restrict__ q1, int8_t* __restrict__ q2,
    float* __restrict__ scale)
{
    const int row = blockIdx.x;
    const int tid = threadIdx.x;
    const int LEN = 128 * NPT;
    const float* s = src + (size_t)row * lds;

    float4 v[NPT / 4];
    float m = 0.0f;
#pragma unroll
    for (int p = 0; p < NPT / 4; p++) {
        v[p] = *(const float4*)(s + (size_t)(p * 128 + tid) * 4);
        m = fmaxf(m, fmaxf(fmaxf(fabsf(v[p].x), fabsf(v[p].y)),
                           fmaxf(fabsf(v[p].z), fabsf(v[p].w))));
    }
#pragma unroll
    for (int o = 16; o > 0; o >>= 1) m = fmaxf(m, __shfl_xor_sync(~0u, m, o));
    __shared__ float sm[4];
    const int warp = tid >> 5, lane = tid & 31;
    if (lane == 0) sm[warp] = m;
    __syncthreads();
    m = fmaxf(fmaxf(sm[0], sm[1]), fmaxf(sm[2], sm[3]));
    m = fmaxf(m, 1e-30f);

    const float s1 = m * (1.0f / 127.0f);
    const float inv1 = 127.0f / m;
    const float inv2 = 254.0f / s1;
    if (tid == 0) scale[row] = s1;

    int* q1p = (int*)(q1 + (size_t)row * LEN);
    int* q2p = (int*)(q2 + (size_t)row * LEN);
#pragma unroll
    for (int p = 0; p < NPT / 4; p++) {
        float xs[4] = {v[p].x, v[p].y, v[p].z, v[p].w};
        int pk1 = 0, pk2 = 0;
#pragma unroll
        for (int e = 0; e < 4; e++) {
            int a = __float2int_rn(xs[e] * inv1);
            float r = xs[e] - s1 * (float)a;
            int b2 = __float2int_rn(r * inv2);
            b2 = max(-127, min(127, b2));
            pk1 |= (a & 255) << (8 * e);
            pk2 |= (b2 & 255) << (8 * e);
        }
        q1p[p * 128 + tid] = pk1;
        q2p[p * 128 + tid] = pk2;
    }
}

// ---------------------------------------------------------------------------
// int8 split tensor-core GEMM (IMMA m16n8k32):
//   C[m,n] = sA[m]*sB[n]*(acc_hi + acc_x/254) + bias[n]   (MODE1: +gelu)
// 128x128 block, 8 warps (2x4), 64x32/warp, K chunks of 64 (bytes),
// 3-stage cp.async pipeline.
// ---------------------------------------------------------------------------
#define AROW 80                  // padded row stride (64B data + 16 pad)
#define TILE_B (128 * AROW)      // 10240
#define ST_A1 0
#define ST_A2 TILE_B
#define ST_B1 (2 * TILE_B)
#define ST_B2 (3 * TILE_B)
#define STAGE_B (4 * TILE_B)     // 40960
#define IG_SMEM (3 * STAGE_B)    // 122880

template <int MODE>
__global__ void __launch_bounds__(256) ig_gemm(
    const int8_t* __restrict__ Aq1, const int8_t* __restrict__ Aq2,
    const float* __restrict__ sA, int lda,
    const int8_t* __restrict__ Bq1, const int8_t* __restrict__ Bq2,
    const float* __restrict__ sB, int ldb,
    const float* __restrict__ bias,
    float* __restrict__ C, int ldc, int K)
{
    extern __shared__ char smem[];
    const uint32_t sb = smem_u32(smem);
    const int tid = threadIdx.x;
    const int wid = tid >> 5, lane = tid & 31;
    const int wm = wid >> 2;             // 0..1
    const int wn = wid & 3;              // 0..3
    const int brow = blockIdx.y * 128;
    const int bcol = blockIdx.x * 128;

    // loader mapping: 512 (row,16B-seg) pairs per array, 2 per thread
    int rowg[2], seg16[2], smoff[2];
#pragma unroll
    for (int t = 0; t < 2; t++) {
        int sid = tid + (t << 8);
        rowg[t] = sid >> 2;
        seg16[t] = (sid & 3) * 16;
        smoff[t] = rowg[t] * AROW + seg16[t];
    }
    const int8_t* pA1 = Aq1 + (size_t)brow * lda;
    const int8_t* pA2 = Aq2 + (size_t)brow * lda;
    const int8_t* pB1 = Bq1 + (size_t)bcol * ldb;
    const int8_t* pB2 = Bq2 + (size_t)bcol * ldb;

    const uint32_t a_loff = (uint32_t)((wm * 64 + (lane & 15)) * AROW + (lane >> 4) * 16);
    const uint32_t b_loff = (uint32_t)((wn * 32 + (lane & 7) + ((lane >> 4) << 3)) * AROW
                                       + ((lane >> 3) & 1) * 16);

    int acc1[4][4][4];   // q1*r1
    int accx[4][4][4];   // q1*r2 + q2*r1
#pragma unroll
    for (int i = 0; i < 4; i++)
#pragma unroll
        for (int j = 0; j < 4; j++)
#pragma unroll
            for (int e = 0; e < 4; e++) { acc1[i][j][e] = 0; accx[i][j][e] = 0; }

    const int NC = K >> 6;               // 64-byte chunks

#define IG_ISSUE(snb, kc) do {                                           \
    const uint32_t _s = (snb);                                           \
    _Pragma("unroll")                                                    \
    for (int t = 0; t < 2; t++) {                                        \
        const int go  = rowg[t] * lda + seg16[t] + (kc);                 \
        const int gob = rowg[t] * ldb + seg16[t] + (kc);                 \
        cp16(_s + ST_A1 + smoff[t], pA1 + go);                           \
        cp16(_s + ST_A2 + smoff[t], pA2 + go);                           \
        cp16(_s + ST_B1 + smoff[t], pB1 + gob);                          \
        cp16(_s + ST_B2 + smoff[t], pB2 + gob);                          \
    }                                                                    \
    cp_commit();                                                         \
} while (0)

    // prologue: stages 0, 1
    IG_ISSUE(sb, 0);
    IG_ISSUE(sb + STAGE_B, 64);

    for (int c = 0; c < NC; c++) {
        if (c + 2 < NC) { cp_wait<1>(); } else { cp_wait<0>(); }
        __syncthreads();
        if (c + 2 < NC) {
            IG_ISSUE(sb + ((c + 2) % 3) * STAGE_B, (c + 2) << 6);
        }

        const uint32_t base = sb + (c % 3) * STAGE_B;
#pragma unroll
        for (int kk = 0; kk < 2; kk++) {
            const uint32_t kb = kk * 32;
            uint32_t b1r[8], b2r[8];
#pragma unroll
            for (int j = 0; j < 2; j++) {
                ldmx4(&b1r[j * 4], base + ST_B1 + j * (16 * AROW) + kb + b_loff);
                ldmx4(&b2r[j * 4], base + ST_B2 + j * (16 * AROW) + kb + b_loff);
            }
#pragma unroll
            for (int i = 0; i < 4; i++) {
                uint32_t a1[4], a2[4];
                ldmx4(a1, base + ST_A1 + i * (16 * AROW) + kb + a_loff);
                ldmx4(a2, base + ST_A2 + i * (16 * AROW) + kb + a_loff);
#pragma unroll
                for (int jn = 0; jn < 4; jn++) {
                    const uint32_t* bp1 = &b1r[(jn >> 1) * 4 + (jn & 1) * 2];
                    const uint32_t* bp2 = &b2r[(jn >> 1) * 4 + (jn & 1) * 2];
                    imma(acc1[i][jn], a1, bp1);
                    imma(accx[i][jn], a1, bp2);
                    imma(accx[i][jn], a2, bp1);
                }
            }
        }
    }
#undef IG_ISSUE

    // Epilogue: dequantize
    const int lm = lane >> 2;
    const int ln = (lane & 3) * 2;
    const float inv254 = 1.0f / 254.0f;
#pragma unroll
    for (int i = 0; i < 4; i++) {
        const int r0 = brow + wm * 64 + i * 16 + lm;
        const float sa0 = sA[r0];
        const float sa1 = sA[r0 + 8];
#pragma unroll
        for (int jn = 0; jn < 4; jn++) {
            const int n = bcol + wn * 32 + jn * 8 + ln;
            const float sb0 = sB[n], sb1 = sB[n + 1];
            const float b0 = bias ? bias[n] : 0.0f;
            const float b1 = bias ? bias[n + 1] : 0.0f;
            float d0 = sa0 * sb0 * ((float)acc1[i][jn][0] + (float)accx[i][jn][0] * inv254) + b0;
            float d1 = sa0 * sb1 * ((float)acc1[i][jn][1] + (float)accx[i][jn][1] * inv254) + b1;
            float d2 = sa1 * sb0 * ((float)acc1[i][jn][2] + (float)accx[i][jn][2] * inv254) + b0;
            float d3 = sa1 * sb1 * ((float)acc1[i][jn][3] + (float)accx[i][jn][3] * inv254) + b1;
            if (MODE == 1) {
                d0 = gelu_exact(d0); d1 = gelu_exact(d1);
                d2 = gelu_exact(d2); d3 = gelu_exact(d3);
            }
            *(float2*)(C + (size_t)r0 * ldc + n) = make_float2(d0, d1);
            *(float2*)(C + (size_t)(r0 + 8) * ldc + n) = make_float2(d2, d3);
        }
    }
}

// ---------------------------------------------------------------------------
// Attention: one block per (b,h). S=64, HD=64 in smem.
// ---------------------------------------------------------------------------
__global__ void __launch_bounds__(256) attn_kernel(
    const float* __restrict__ qkv, float* __restrict__ out)
{
    const int bh = blockIdx.x;
    const int b = bh >> 3;
    const int h = bh & 7;

    __shared__ __align__(16) float Qs[64][64];
    __shared__ __align__(16) float Kt[64][64];
    __shared__ __align__(16) float Vs[64][64];

    const int tid = threadIdx.x;
    const float* base = qkv + (size_t)b * S * (3 * D) + h * HD;

    const int r = tid >> 2;
    const int c0 = (tid & 3) * 16;
#pragma unroll
    for (int i = 0; i < 4; i++) {
        int c = c0 + i * 4;
        float4 qv = *(const float4*)(base + (size_t)r * (3 * D) + c);
        float4 kv = *(const float4*)(base + (size_t)r * (3 * D) + D + c);
        float4 vv = *(const float4*)(base + (size_t)r * (3 * D) + 2 * D + c);
        *(float4*)(&Qs[r][c]) = qv;
        *(float4*)(&Vs[r][c]) = vv;
        Kt[c + 0][r] = kv.x; Kt[c + 1][r] = kv.y;
        Kt[c + 2][r] = kv.z; Kt[c + 3][r] = kv.w;
    }
    __syncthreads();

    float sc[16];
#pragma unroll
    for (int k = 0; k < 16; k++) {
        int idx = tid + k * 256;
        int i = idx >> 6, j = idx & 63;
        float s = 0.0f;
#pragma unroll
        for (int d = 0; d < 64; d++) s = fmaf(Qs[i][d], Kt[d][j], s);
        sc[k] = s * 0.125f;
    }
    __syncthreads();

    float (*P)[64] = Qs;
#pragma unroll
    for (int k = 0; k < 16; k++) {
        int idx = tid + k * 256;
        P[idx >> 6][idx & 63] = sc[k];
    }
    __syncthreads();

    const int warp = tid >> 5, lane = tid & 31;
#pragma unroll
    for (int rr = 0; rr < 8; rr++) {
        int i = warp + rr * 8;
        float v0 = P[i][lane], v1 = P[i][lane + 32];
        float mx = fmaxf(v0, v1);
#pragma unroll
        for (int o = 16; o > 0; o >>= 1) mx = fmaxf(mx, __shfl_xor_sync(~0u, mx, o));
        float e0 = __expf(v0 - mx), e1 = __expf(v1 - mx);
        float s = e0 + e1;
#pragma unroll
        for (int o = 16; o > 0; o >>= 1) s += __shfl_xor_sync(~0u, s, o);
        float inv = 1.0f / s;
        P[i][lane] = e0 * inv;
        P[i][lane + 32] = e1 * inv;
    }
    __syncthreads();

#pragma unroll
    for (int k = 0; k < 16; k++) {
        int idx = tid + k * 256;
        int i = idx >> 6, d = idx & 63;
        float o = 0.0f;
#pragma unroll
        for (int j = 0; j < 64; j++) o = fmaf(P[i][j], Vs[j][d], o);
        out[(size_t)(b * S + i) * D + h * HD + d] = o;
    }
}

// ---------------------------------------------------------------------------
// Fused residual add + LayerNorm + two-level int8 row quantization
// ---------------------------------------------------------------------------
__global__ void __launch_bounds__(128) add_ln_kernel(
    float* __restrict__ x, const float* __restrict__ y,
    const float* __restrict__ g, const float* __restrict__ bta,
    int8_t* __restrict__ q1, int8_t* __restrict__ q2,
    float* __restrict__ scale)
{
    const int row = blockIdx.x;
    const int tid = threadIdx.x;
    const int warp = tid >> 5, lane = tid & 31;

    float4 xv = *(const float4*)(x + (size_t)row * D + tid * 4);
    float4 yv = *(const float4*)(y + (size_t)row * D + tid * 4);
    float s0 = xv.x + yv.x, s1v = xv.y + yv.y, s2 = xv.z + yv.z, s3 = xv.w + yv.w;

    float sum = s0 + s1v + s2 + s3;
    float sq = fmaf(s0, s0, fmaf(s1v, s1v, fmaf(s2, s2, s3 * s3)));
#pragma unroll
    for (int o = 16; o > 0; o >>= 1) {
        sum += __shfl_xor_sync(~0u, sum, o);
        sq  += __shfl_xor_sync(~0u, sq, o);
    }
    __shared__ float sh[8];
    __shared__ float smax[4];
    if (lane == 0) { sh[warp] = sum; sh[4 + warp] = sq; }
    __syncthreads();
    sum = sh[0] + sh[1] + sh[2] + sh[3];
    sq  = sh[4] + sh[5] + sh[6] + sh[7];

    const float mu = sum * (1.0f / D);
    const float var = sq * (1.0f / D) - mu * mu;
    const float inv = rsqrtf(var + EPS);

    float4 gv = *(const float4*)(g + tid * 4);
    float4 bv = *(const float4*)(bta + tid * 4);
    float o0 = (s0 - mu) * inv * gv.x + bv.x;
    float o1 = (s1v - mu) * inv * gv.y + bv.y;
    float o2 = (s2 - mu) * inv * gv.z + bv.z;
    float o3 = (s3 - mu) * inv * gv.w + bv.w;
    *(float4*)(x + (size_t)row * D + tid * 4) = make_float4(o0, o1, o2, o3);

    // rowmax for quantization
    float m = fmaxf(fmaxf(fabsf(o0), fabsf(o1)), fmaxf(fabsf(o2), fabsf(o3)));
#pragma unroll
    for (int o = 16; o > 0; o >>= 1) m = fmaxf(m, __shfl_xor_sync(~0u, m, o));
    if (lane == 0) smax[warp] = m;
    __syncthreads();
    m = fmaxf(fmaxf(smax[0], smax[1]), fmaxf(smax[2], smax[3]));
    m = fmaxf(m, 1e-30f);

    const float s1q = m * (1.0f / 127.0f);
    const float i1 = 127.0f / m;
    const float i2 = 254.0f / s1q;
    if (tid == 0) scale[row] = s1q;

    float xs[4] = {o0, o1, o2, o3};
    int pk1 = 0, pk2 = 0;
#pragma unroll
    for (int e = 0; e < 4; e++) {
        int a = __float2int_rn(xs[e] * i1);
        float rr = xs[e] - s1q * (float)a;
        int b2 = __float2int_rn(rr * i2);
        b2 = max(-127, min(127, b2));
        pk1 |= (a & 255) << (8 * e);
        pk2 |= (b2 & 255) << (8 * e);
    }
    ((int*)(q1 + (size_t)row * D))[tid] = pk1;
    ((int*)(q2 + (size_t)row * D))[tid] = pk2;
}

// ---------------------------------------------------------------------------
// Pairwise policy head
// ---------------------------------------------------------------------------
#define PCH 128

__global__ void __launch_bounds__(256) pairwise_kernel(
    const float* __restrict__ F, const float* __restrict__ T,
    const float* __restrict__ bm1, const float* __restrict__ wm2,
    const float* __restrict__ bm2v, float* __restrict__ out)
{
    const int b = blockIdx.x >> 3;
    const int ft = blockIdx.x & 7;

    __shared__ float Fs[8][PCH + 1];
    __shared__ float Ts[64][PCH + 1];
    __shared__ __align__(16) float ws[PCH];

    const int tid = threadIdx.x;
    const int f = tid & 7;
    const int t0 = (tid >> 3) * 2;

    float acc0 = 0.0f, acc1v = 0.0f;
    const float* Fbase = F + ((size_t)b * S + ft * 8) * FF;
    const float* Tbase = T + (size_t)b * S * FF;

    for (int c = 0; c < FF; c += PCH) {
        {
            int fr = tid >> 5, cc = (tid & 31) * 4;
            float4 fv = *(const float4*)(Fbase + (size_t)fr * FF + c + cc);
            Fs[fr][cc + 0] = fv.x; Fs[fr][cc + 1] = fv.y;
            Fs[fr][cc + 2] = fv.z; Fs[fr][cc + 3] = fv.w;
        }
        if (tid < 32) *(float4*)(&ws[tid * 4]) = *(const float4*)(wm2 + c + tid * 4);
        {
            int tr = tid >> 2, tcc0 = (tid & 3) * 32;
#pragma unroll
            for (int i = 0; i < 8; i++) {
                int cc = tcc0 + i * 4;
                float4 tv = *(const float4*)(Tbase + (size_t)tr * FF + c + cc);
                float4 bb = *(const float4*)(bm1 + c + cc);
                Ts[tr][cc + 0] = tv.x + bb.x;
                Ts[tr][cc + 1] = tv.y + bb.y;
                Ts[tr][cc + 2] = tv.z + bb.z;
                Ts[tr][cc + 3] = tv.w + bb.w;
            }
        }
        __syncthreads();

#pragma unroll 4
        for (int hh = 0; hh < PCH; hh++) {
            float fv = Fs[f][hh];
            float w = ws[hh];
            float a0 = fv + Ts[t0][hh];
            float a1 = fv + Ts[t0 + 1][hh];
            acc0  = fmaf(gelu_exact(a0), w, acc0);
            acc1v = fmaf(gelu_exact(a1), w, acc1v);
        }
        __syncthreads();
    }

    const float bm2s = bm2v[0];
    const int fg = ft * 8 + f;
    float* orow = out + ((size_t)b * S + fg) * S;
    orow[t0]     = acc0 + bm2s;
    orow[t0 + 1] = acc1v + bm2s;
}

// ---------------------------------------------------------------------------
// Launcher
// ---------------------------------------------------------------------------
extern "C" void kernel_launch(void* const* d_in, const int* in_sizes, int n_in,
                              void* d_out, int out_size)
{
    const float* emb   = (const float*)d_in[0];
    const float* Wqkv  = (const float*)d_in[1];
    const float* bqkv  = (const float*)d_in[2];
    const float* Wo    = (const float*)d_in[3];
    const float* bo    = (const float*)d_in[4];
    const float* ln1_g = (const float*)d_in[5];
    const float* ln1_b = (const float*)d_in[6];
    const float* ln2_g = (const float*)d_in[7];
    const float* ln2_b = (const float*)d_in[8];
    const float* W1    = (const float*)d_in[9];
    const float* b1    = (const float*)d_in[10];
    const float* W2    = (const float*)d_in[11];
    const float* b2    = (const float*)d_in[12];
    const float* Wm1   = (const float*)d_in[13];
    const float* bm1   = (const float*)d_in[14];
    const float* Wm2   = (const float*)d_in[15];
    const float* bm2   = (const float*)d_in[16];
    float* out = (float*)d_out;

    float *x, *qkvb, *ao, *tmp, *hb, *fb, *tb;
    cudaGetSymbolAddress((void**)&x, g_x);
    cudaGetSymbolAddress((void**)&qkvb, g_qkv);
    cudaGetSymbolAddress((void**)&ao, g_ao);
    cudaGetSymbolAddress((void**)&tmp, g_tmp);
    cudaGetSymbolAddress((void**)&hb, g_h);
    cudaGetSymbolAddress((void**)&fb, g_f);
    cudaGetSymbolAddress((void**)&tb, g_t);

    int8_t *x1, *x2, *ao1, *ao2, *h1, *h2;
    int8_t *wq1, *wq2, *wo1, *wo2, *w11, *w12, *w21, *w22, *mf1, *mf2, *mt1, *mt2;
    float *sx, *sao, *sh, *swq, *swo, *sw1, *sw2, *smf, *smt;
    cudaGetSymbolAddress((void**)&x1, q_x1);   cudaGetSymbolAddress((void**)&x2, q_x2);
    cudaGetSymbolAddress((void**)&ao1, q_ao1); cudaGetSymbolAddress((void**)&ao2, q_ao2);
    cudaGetSymbolAddress((void**)&h1, q_h1);   cudaGetSymbolAddress((void**)&h2, q_h2);
    cudaGetSymbolAddress((void**)&wq1, q_wqkv1); cudaGetSymbolAddress((void**)&wq2, q_wqkv2);
    cudaGetSymbolAddress((void**)&wo1, q_wo1); cudaGetSymbolAddress((void**)&wo2, q_wo2);
    cudaGetSymbolAddress((void**)&w11, q_w11); cudaGetSymbolAddress((void**)&w12, q_w12);
    cudaGetSymbolAddress((void**)&w21, q_w21); cudaGetSymbolAddress((void**)&w22, q_w22);
    cudaGetSymbolAddress((void**)&mf1, q_wm1f1); cudaGetSymbolAddress((void**)&mf2, q_wm1f2);
    cudaGetSymbolAddress((void**)&mt1, q_wm1t1); cudaGetSymbolAddress((void**)&mt2, q_wm1t2);
    cudaGetSymbolAddress((void**)&sx, s_x);    cudaGetSymbolAddress((void**)&sao, s_ao);
    cudaGetSymbolAddress((void**)&sh, s_h);    cudaGetSymbolAddress((void**)&swq, s_wqkv);
    cudaGetSymbolAddress((void**)&swo, s_wo);  cudaGetSymbolAddress((void**)&sw1, s_w1);
    cudaGetSymbolAddress((void**)&sw2, s_w2);  cudaGetSymbolAddress((void**)&smf, s_wm1f);
    cudaGetSymbolAddress((void**)&smt, s_wm1t);

    cudaFuncSetAttribute(ig_gemm<0>, cudaFuncAttributeMaxDynamicSharedMemorySize, IG_SMEM);
    cudaFuncSetAttribute(ig_gemm<1>, cudaFuncAttributeMaxDynamicSharedMemorySize, IG_SMEM);

    cudaMemcpyAsync(x, emb, (size_t)M_TOT * D * sizeof(float),
                    cudaMemcpyDeviceToDevice);

    // quantize weights + embedding
    quant_rows<4><<<LAYERS * 3 * D, 128>>>(Wqkv, D, wq1, wq2, swq);
    quant_rows<4><<<LAYERS * D, 128>>>(Wo, D, wo1, wo2, swo);
    quant_rows<4><<<LAYERS * FF, 128>>>(W1, D, w11, w12, sw1);
    quant_rows<8><<<LAYERS * D, 128>>>(W2, FF, w21, w22, sw2);
    quant_rows<4><<<FF, 128>>>(Wm1, 2 * D, mf1, mf2, smf);
    quant_rows<4><<<FF, 128>>>(Wm1 + D, 2 * D, mt1, mt2, smt);
    quant_rows<4><<<M_TOT, 128>>>(emb, D, x1, x2, sx);

    const dim3 gQKV(3 * D / 128, M_TOT / 128);
    const dim3 gD  (D / 128,     M_TOT / 128);
    const dim3 gFF (FF / 128,    M_TOT / 128);

    for (int l = 0; l < LAYERS; l++) {
        ig_gemm<0><<<gQKV, 256, IG_SMEM>>>(
            x1, x2, sx, D,
            wq1 + (size_t)l * 3 * D * D, wq2 + (size_t)l * 3 * D * D,
            swq + (size_t)l * 3 * D, D,
            bqkv + (size_t)l * 3 * D, qkvb, 3 * D, D);
        attn_kernel<<<B * H, 256>>>(qkvb, ao);
        quant_rows<4><<<M_TOT, 128>>>(ao, D, ao1, ao2, sao);
        ig_gemm<0><<<gD, 256, IG_SMEM>>>(
            ao1, ao2, sao, D,
            wo1 + (size_t)l * D * D, wo2 + (size_t)l * D * D,
            swo + (size_t)l * D, D,
            bo + (size_t)l * D, tmp, D, D);
        add_ln_kernel<<<M_TOT, 128>>>(x, tmp, ln1_g + (size_t)l * D,
                                      ln1_b + (size_t)l * D, x1, x2, sx);
        ig_gemm<1><<<gFF, 256, IG_SMEM>>>(
            x1, x2, sx, D,
            w11 + (size_t)l * FF * D, w12 + (size_t)l * FF * D,
            sw1 + (size_t)l * FF, D,
            b1 + (size_t)l * FF, hb, FF, D);
        quant_rows<8><<<M_TOT, 128>>>(hb, FF, h1, h2, sh);
        ig_gemm<0><<<gD, 256, IG_SMEM>>>(
            h1, h2, sh, FF,
            w21 + (size_t)l * D * FF, w22 + (size_t)l * D * FF,
            sw2 + (size_t)l * D, FF,
            b2 + (size_t)l * D, tmp, D, FF);
        add_ln_kernel<<<M_TOT, 128>>>(x, tmp, ln2_g + (size_t)l * D,
                                      ln2_b + (size_t)l * D, x1, x2, sx);
    }

    // Policy head
    ig_gemm<0><<<gFF, 256, IG_SMEM>>>(
        x1, x2, sx, D, mf1, mf2, smf, D, nullptr, fb, FF, D);
    ig_gemm<0><<<gFF, 256, IG_SMEM>>>(
        x1, x2, sx, D, mt1, mt2, smt, D, nullptr, tb, FF, D);
    pairwise_kernel<<<B * 8, 256>>>(fb, tb, bm1, Wm2, bm2, out);
}

// round 6
// speedup vs baseline: 2.8403x; 1.0001x over previous
#include <cuda_runtime.h>
#include <cuda_bf16.h>
#include <math.h>
#include <stdint.h>

#define LAYERS 4
#define D 512
#define H 8
#define HD 64
#define FF 1024
#define B 64
#define S 64
#define M_TOT (B * S)
#define EPS 1e-5f

// ---------------------------------------------------------------------------
// Scratch buffers
// ---------------------------------------------------------------------------
__device__ float g_x[M_TOT * D];
__device__ float g_qkv[M_TOT * 3 * D];
__device__ float g_ao[M_TOT * D];
__device__ float g_tmp[M_TOT * D];
__device__ float g_h[M_TOT * FF];
__device__ float g_f[M_TOT * FF];
__device__ float g_t[M_TOT * FF];

// int8 two-level quantized operands
__device__ int8_t q_x1[M_TOT * D],  q_x2[M_TOT * D];
__device__ int8_t q_ao1[M_TOT * D], q_ao2[M_TOT * D];
__device__ int8_t q_h1[M_TOT * FF], q_h2[M_TOT * FF];
__device__ int8_t q_wqkv1[LAYERS * 3 * D * D], q_wqkv2[LAYERS * 3 * D * D];
__device__ int8_t q_wo1[LAYERS * D * D],       q_wo2[LAYERS * D * D];
__device__ int8_t q_w11[LAYERS * FF * D],      q_w12[LAYERS * FF * D];
__device__ int8_t q_w21[LAYERS * D * FF],      q_w22[LAYERS * D * FF];
__device__ int8_t q_wm1f1[FF * D], q_wm1f2[FF * D];
__device__ int8_t q_wm1t1[FF * D], q_wm1t2[FF * D];

// per-row scales
__device__ float s_x[M_TOT], s_ao[M_TOT], s_h[M_TOT];
__device__ float s_wqkv[LAYERS * 3 * D], s_wo[LAYERS * D];
__device__ float s_w1[LAYERS * FF], s_w2[LAYERS * D];
__device__ float s_wm1f[FF], s_wm1t[FF];

__device__ __forceinline__ float gelu_exact(float x) {
    return 0.5f * x * (1.0f + erff(x * 0.70710678118654752f));
}

__device__ __forceinline__ uint32_t smem_u32(const void* p) {
    uint32_t a;
    asm("{ .reg .u64 t; cvta.to.shared.u64 t, %1; cvt.u32.u64 %0, t; }"
        : "=r"(a) : "l"(p));
    return a;
}

__device__ __forceinline__ void ldmx4(uint32_t* r, uint32_t addr) {
    asm volatile("ldmatrix.sync.aligned.m8n8.x4.shared.b16 {%0,%1,%2,%3}, [%4];"
                 : "=r"(r[0]), "=r"(r[1]), "=r"(r[2]), "=r"(r[3]) : "r"(addr));
}

__device__ __forceinline__ void imma(int* d, const uint32_t* a, const uint32_t* b) {
    asm volatile(
        "mma.sync.aligned.m16n8k32.row.col.s32.s8.s8.s32 "
        "{%0,%1,%2,%3}, {%4,%5,%6,%7}, {%8,%9}, {%0,%1,%2,%3};"
        : "+r"(d[0]), "+r"(d[1]), "+r"(d[2]), "+r"(d[3])
        : "r"(a[0]), "r"(a[1]), "r"(a[2]), "r"(a[3]), "r"(b[0]), "r"(b[1]));
}

__device__ __forceinline__ void cp16(uint32_t saddr, const void* gptr) {
    asm volatile("cp.async.cg.shared.global [%0], [%1], 16;"
                 :: "r"(saddr), "l"(gptr));
}
__device__ __forceinline__ void cp_commit() {
    asm volatile("cp.async.commit_group;");
}
template <int N>
__device__ __forceinline__ void cp_wait() {
    asm volatile("cp.async.wait_group %0;" :: "n"(N));
}

// ---------------------------------------------------------------------------
// Row-wise two-level int8 quantization: x ~ s*(q1 + q2/254), s = rowmax/127.
// ---------------------------------------------------------------------------
template <int NPT>
__global__ void __launch_bounds__(128) quant_rows(
    const float* __restrict__ src, int lds,
    int8_t* __restrict__ q1, int8_t* __restrict__ q2,
    float* __restrict__ scale)
{
    const int row = blockIdx.x;
    const int tid = threadIdx.x;
    const int LEN = 128 * NPT;
    const float* s = src + (size_t)row * lds;

    float4 v[NPT / 4];
    float m = 0.0f;
#pragma unroll
    for (int p = 0; p < NPT / 4; p++) {
        v[p] = *(const float4*)(s + (size_t)(p * 128 + tid) * 4);
        m = fmaxf(m, fmaxf(fmaxf(fabsf(v[p].x), fabsf(v[p].y)),
                           fmaxf(fabsf(v[p].z), fabsf(v[p].w))));
    }
#pragma unroll
    for (int o = 16; o > 0; o >>= 1) m = fmaxf(m, __shfl_xor_sync(~0u, m, o));
    __shared__ float sm[4];
    const int warp = tid >> 5, lane = tid & 31;
    if (lane == 0) sm[warp] = m;
    __syncthreads();
    m = fmaxf(fmaxf(sm[0], sm[1]), fmaxf(sm[2], sm[3]));
    m = fmaxf(m, 1e-30f);

    const float s1 = m * (1.0f / 127.0f);
    const float inv1 = 127.0f / m;
    const float inv2 = 254.0f / s1;
    if (tid == 0) scale[row] = s1;

    int* q1p = (int*)(q1 + (size_t)row * LEN);
    int* q2p = (int*)(q2 + (size_t)row * LEN);
#pragma unroll
    for (int p = 0; p < NPT / 4; p++) {
        float xs[4] = {v[p].x, v[p].y, v[p].z, v[p].w};
        int pk1 = 0, pk2 = 0;
#pragma unroll
        for (int e = 0; e < 4; e++) {
            int a = __float2int_rn(xs[e] * inv1);
            float r = xs[e] - s1 * (float)a;
            int b2 = __float2int_rn(r * inv2);
            b2 = max(-127, min(127, b2));
            pk1 |= (a & 255) << (8 * e);
            pk2 |= (b2 & 255) << (8 * e);
        }
        q1p[p * 128 + tid] = pk1;
        q2p[p * 128 + tid] = pk2;
    }
}

// ---------------------------------------------------------------------------
// int8 split tensor-core GEMM (IMMA m16n8k32):
//   C[m,n] = sA[m]*sB[n]*(acc_hi + acc_x/254) + bias[n]   (MODE1: +gelu)
// 128x64 block, 8 warps (4x2), 32x32/warp, K chunks of 64 B,
// 2-stage cp.async pipeline, 2 CTAs/SM.
// ---------------------------------------------------------------------------
#define AROW 80
#define A_TILE_B (128 * AROW)    // 10240
#define B_TILE_B (64 * AROW)     // 5120
#define ST_A1 0
#define ST_A2 A_TILE_B
#define ST_B1 (2 * A_TILE_B)
#define ST_B2 (2 * A_TILE_B + B_TILE_B)
#define STAGE_B (2 * A_TILE_B + 2 * B_TILE_B)   // 30720
#define IG_SMEM (2 * STAGE_B)                    // 61440

template <int MODE>
__global__ void __launch_bounds__(256, 2) ig_gemm(
    const int8_t* __restrict__ Aq1, const int8_t* __restrict__ Aq2,
    const float* __restrict__ sA, int lda,
    const int8_t* __restrict__ Bq1, const int8_t* __restrict__ Bq2,
    const float* __restrict__ sB, int ldb,
    const float* __restrict__ bias,
    float* __restrict__ C, int ldc, int K)
{
    extern __shared__ char smem[];
    const uint32_t sb = smem_u32(smem);
    const int tid = threadIdx.x;
    const int wid = tid >> 5, lane = tid & 31;
    const int wm = wid >> 1;             // 0..3 (32 rows each)
    const int wn = wid & 1;              // 0..1 (32 cols each)
    const int brow = blockIdx.y * 128;
    const int bcol = blockIdx.x * 64;

    // loader mapping: A = 512 (row,seg16) pairs (2/thread), B = 256 (1/thread)
    int rowgA[2], segA[2], smoffA[2];
#pragma unroll
    for (int t = 0; t < 2; t++) {
        int sid = tid + (t << 8);
        rowgA[t] = sid >> 2;
        segA[t] = (sid & 3) * 16;
        smoffA[t] = rowgA[t] * AROW + segA[t];
    }
    const int rowgB = tid >> 2;
    const int segB = (tid & 3) * 16;
    const int smoffB = rowgB * AROW + segB;

    const int8_t* pA1 = Aq1 + (size_t)brow * lda;
    const int8_t* pA2 = Aq2 + (size_t)brow * lda;
    const int8_t* pB1 = Bq1 + (size_t)bcol * ldb;
    const int8_t* pB2 = Bq2 + (size_t)bcol * ldb;

    const uint32_t a_loff = (uint32_t)((wm * 32 + (lane & 15)) * AROW + (lane >> 4) * 16);
    const uint32_t b_loff = (uint32_t)((wn * 32 + (lane & 7) + ((lane >> 4) << 3)) * AROW
                                       + ((lane >> 3) & 1) * 16);

    int acc1[2][4][4];
    int accx[2][4][4];
#pragma unroll
    for (int i = 0; i < 2; i++)
#pragma unroll
        for (int j = 0; j < 4; j++)
#pragma unroll
            for (int e = 0; e < 4; e++) { acc1[i][j][e] = 0; accx[i][j][e] = 0; }

    const int NC = K >> 6;

#define IG_ISSUE(snb, kc) do {                                           \
    const uint32_t _s = (snb);                                           \
    _Pragma("unroll")                                                    \
    for (int t = 0; t < 2; t++) {                                        \
        const int go = rowgA[t] * lda + segA[t] + (kc);                  \
        cp16(_s + ST_A1 + smoffA[t], pA1 + go);                          \
        cp16(_s + ST_A2 + smoffA[t], pA2 + go);                          \
    }                                                                    \
    {                                                                    \
        const int gob = rowgB * ldb + segB + (kc);                       \
        cp16(_s + ST_B1 + smoffB, pB1 + gob);                            \
        cp16(_s + ST_B2 + smoffB, pB2 + gob);                            \
    }                                                                    \
    cp_commit();                                                         \
} while (0)

    IG_ISSUE(sb, 0);

    for (int c = 0; c < NC; c++) {
        if (c + 1 < NC) {
            IG_ISSUE(sb + ((c + 1) & 1) * STAGE_B, (c + 1) << 6);
            cp_wait<1>();
        } else {
            cp_wait<0>();
        }
        __syncthreads();

        const uint32_t base = sb + (c & 1) * STAGE_B;
#pragma unroll
        for (int kk = 0; kk < 2; kk++) {
            const uint32_t kb = kk * 32;
            uint32_t b1r[8], b2r[8];
#pragma unroll
            for (int j = 0; j < 2; j++) {
                ldmx4(&b1r[j * 4], base + ST_B1 + j * (16 * AROW) + kb + b_loff);
                ldmx4(&b2r[j * 4], base + ST_B2 + j * (16 * AROW) + kb + b_loff);
            }
#pragma unroll
            for (int i = 0; i < 2; i++) {
                uint32_t a1[4], a2[4];
                ldmx4(a1, base + ST_A1 + i * (16 * AROW) + kb + a_loff);
                ldmx4(a2, base + ST_A2 + i * (16 * AROW) + kb + a_loff);
#pragma unroll
                for (int jn = 0; jn < 4; jn++) {
                    const uint32_t* bp1 = &b1r[(jn >> 1) * 4 + (jn & 1) * 2];
                    const uint32_t* bp2 = &b2r[(jn >> 1) * 4 + (jn & 1) * 2];
                    imma(acc1[i][jn], a1, bp1);
                    imma(accx[i][jn], a1, bp2);
                    imma(accx[i][jn], a2, bp1);
                }
            }
        }
        __syncthreads();
    }
#undef IG_ISSUE

    // Epilogue: dequantize
    const int lm = lane >> 2;
    const int ln = (lane & 3) * 2;
    const float inv254 = 1.0f / 254.0f;
#pragma unroll
    for (int i = 0; i < 2; i++) {
        const int r0 = brow + wm * 32 + i * 16 + lm;
        const float sa0 = sA[r0];
        const float sa1 = sA[r0 + 8];
#pragma unroll
        for (int jn = 0; jn < 4; jn++) {
            const int n = bcol + wn * 32 + jn * 8 + ln;
            const float sb0 = sB[n], sb1 = sB[n + 1];
            const float b0 = bias ? bias[n] : 0.0f;
            const float b1 = bias ? bias[n + 1] : 0.0f;
            float d0 = sa0 * sb0 * ((float)acc1[i][jn][0] + (float)accx[i][jn][0] * inv254) + b0;
            float d1 = sa0 * sb1 * ((float)acc1[i][jn][1] + (float)accx[i][jn][1] * inv254) + b1;
            float d2 = sa1 * sb0 * ((float)acc1[i][jn][2] + (float)accx[i][jn][2] * inv254) + b0;
            float d3 = sa1 * sb1 * ((float)acc1[i][jn][3] + (float)accx[i][jn][3] * inv254) + b1;
            if (MODE == 1) {
                d0 = gelu_exact(d0); d1 = gelu_exact(d1);
                d2 = gelu_exact(d2); d3 = gelu_exact(d3);
            }
            *(float2*)(C + (size_t)r0 * ldc + n) = make_float2(d0, d1);
            *(float2*)(C + (size_t)(r0 + 8) * ldc + n) = make_float2(d2, d3);
        }
    }
}

// ---------------------------------------------------------------------------
// Attention: one block per (b,h). S=64, HD=64 in smem.
// ---------------------------------------------------------------------------
__global__ void __launch_bounds__(256) attn_kernel(
    const float* __restrict__ qkv, float* __restrict__ out)
{
    const int bh = blockIdx.x;
    const int b = bh >> 3;
    const int h = bh & 7;

    __shared__ __align__(16) float Qs[64][64];
    __shared__ __align__(16) float Kt[64][64];
    __shared__ __align__(16) float Vs[64][64];

    const int tid = threadIdx.x;
    const float* base = qkv + (size_t)b * S * (3 * D) + h * HD;

    const int r = tid >> 2;
    const int c0 = (tid & 3) * 16;
#pragma unroll
    for (int i = 0; i < 4; i++) {
        int c = c0 + i * 4;
        float4 qv = *(const float4*)(base + (size_t)r * (3 * D) + c);
        float4 kv = *(const float4*)(base + (size_t)r * (3 * D) + D + c);
        float4 vv = *(const float4*)(base + (size_t)r * (3 * D) + 2 * D + c);
        *(float4*)(&Qs[r][c]) = qv;
        *(float4*)(&Vs[r][c]) = vv;
        Kt[c + 0][r] = kv.x; Kt[c + 1][r] = kv.y;
        Kt[c + 2][r] = kv.z; Kt[c + 3][r] = kv.w;
    }
    __syncthreads();

    float sc[16];
#pragma unroll
    for (int k = 0; k < 16; k++) {
        int idx = tid + k * 256;
        int i = idx >> 6, j = idx & 63;
        float s = 0.0f;
#pragma unroll
        for (int d = 0; d < 64; d++) s = fmaf(Qs[i][d], Kt[d][j], s);
        sc[k] = s * 0.125f;
    }
    __syncthreads();

    float (*P)[64] = Qs;
#pragma unroll
    for (int k = 0; k < 16; k++) {
        int idx = tid + k * 256;
        P[idx >> 6][idx & 63] = sc[k];
    }
    __syncthreads();

    const int warp = tid >> 5, lane = tid & 31;
#pragma unroll
    for (int rr = 0; rr < 8; rr++) {
        int i = warp + rr * 8;
        float v0 = P[i][lane], v1 = P[i][lane + 32];
        float mx = fmaxf(v0, v1);
#pragma unroll
        for (int o = 16; o > 0; o >>= 1) mx = fmaxf(mx, __shfl_xor_sync(~0u, mx, o));
        float e0 = __expf(v0 - mx), e1 = __expf(v1 - mx);
        float s = e0 + e1;
#pragma unroll
        for (int o = 16; o > 0; o >>= 1) s += __shfl_xor_sync(~0u, s, o);
        float inv = 1.0f / s;
        P[i][lane] = e0 * inv;
        P[i][lane + 32] = e1 * inv;
    }
    __syncthreads();

#pragma unroll
    for (int k = 0; k < 16; k++) {
        int idx = tid + k * 256;
        int i = idx >> 6, d = idx & 63;
        float o = 0.0f;
#pragma unroll
        for (int j = 0; j < 64; j++) o = fmaf(P[i][j], Vs[j][d], o);
        out[(size_t)(b * S + i) * D + h * HD + d] = o;
    }
}

// ---------------------------------------------------------------------------
// Fused residual add + LayerNorm + two-level int8 row quantization
// ---------------------------------------------------------------------------
__global__ void __launch_bounds__(128) add_ln_kernel(
    float* __restrict__ x, const float* __restrict__ y,
    const float* __restrict__ g, const float* __restrict__ bta,
    int8_t* __restrict__ q1, int8_t* __restrict__ q2,
    float* __restrict__ scale)
{
    const int row = blockIdx.x;
    const int tid = threadIdx.x;
    const int warp = tid >> 5, lane = tid & 31;

    float4 xv = *(const float4*)(x + (size_t)row * D + tid * 4);
    float4 yv = *(const float4*)(y + (size_t)row * D + tid * 4);
    float s0 = xv.x + yv.x, s1v = xv.y + yv.y, s2 = xv.z + yv.z, s3 = xv.w + yv.w;

    float sum = s0 + s1v + s2 + s3;
    float sq = fmaf(s0, s0, fmaf(s1v, s1v, fmaf(s2, s2, s3 * s3)));
#pragma unroll
    for (int o = 16; o > 0; o >>= 1) {
        sum += __shfl_xor_sync(~0u, sum, o);
        sq  += __shfl_xor_sync(~0u, sq, o);
    }
    __shared__ float sh[8];
    __shared__ float smax[4];
    if (lane == 0) { sh[warp] = sum; sh[4 + warp] = sq; }
    __syncthreads();
    sum = sh[0] + sh[1] + sh[2] + sh[3];
    sq  = sh[4] + sh[5] + sh[6] + sh[7];

    const float mu = sum * (1.0f / D);
    const float var = sq * (1.0f / D) - mu * mu;
    const float inv = rsqrtf(var + EPS);

    float4 gv = *(const float4*)(g + tid * 4);
    float4 bv = *(const float4*)(bta + tid * 4);
    float o0 = (s0 - mu) * inv * gv.x + bv.x;
    float o1 = (s1v - mu) * inv * gv.y + bv.y;
    float o2 = (s2 - mu) * inv * gv.z + bv.z;
    float o3 = (s3 - mu) * inv * gv.w + bv.w;
    *(float4*)(x + (size_t)row * D + tid * 4) = make_float4(o0, o1, o2, o3);

    float m = fmaxf(fmaxf(fabsf(o0), fabsf(o1)), fmaxf(fabsf(o2), fabsf(o3)));
#pragma unroll
    for (int o = 16; o > 0; o >>= 1) m = fmaxf(m, __shfl_xor_sync(~0u, m, o));
    if (lane == 0) smax[warp] = m;
    __syncthreads();
    m = fmaxf(fmaxf(smax[0], smax[1]), fmaxf(smax[2], smax[3]));
    m = fmaxf(m, 1e-30f);

    const float s1q = m * (1.0f / 127.0f);
    const float i1 = 127.0f / m;
    const float i2 = 254.0f / s1q;
    if (tid == 0) scale[row] = s1q;

    float xs[4] = {o0, o1, o2, o3};
    int pk1 = 0, pk2 = 0;
#pragma unroll
    for (int e = 0; e < 4; e++) {
        int a = __float2int_rn(xs[e] * i1);
        float rr = xs[e] - s1q * (float)a;
        int b2 = __float2int_rn(rr * i2);
        b2 = max(-127, min(127, b2));
        pk1 |= (a & 255) << (8 * e);
        pk2 |= (b2 & 255) << (8 * e);
    }
    ((int*)(q1 + (size_t)row * D))[tid] = pk1;
    ((int*)(q2 + (size_t)row * D))[tid] = pk2;
}

// ---------------------------------------------------------------------------
// Pairwise policy head
// ---------------------------------------------------------------------------
#define PCH 128

__global__ void __launch_bounds__(256) pairwise_kernel(
    const float* __restrict__ F, const float* __restrict__ T,
    const float* __restrict__ bm1, const float* __restrict__ wm2,
    const float* __restrict__ bm2v, float* __restrict__ out)
{
    const int b = blockIdx.x >> 3;
    const int ft = blockIdx.x & 7;

    __shared__ float Fs[8][PCH + 1];
    __shared__ float Ts[64][PCH + 1];
    __shared__ __align__(16) float ws[PCH];

    const int tid = threadIdx.x;
    const int f = tid & 7;
    const int t0 = (tid >> 3) * 2;

    float acc0 = 0.0f, acc1v = 0.0f;
    const float* Fbase = F + ((size_t)b * S + ft * 8) * FF;
    const float* Tbase = T + (size_t)b * S * FF;

    for (int c = 0; c < FF; c += PCH) {
        {
            int fr = tid >> 5, cc = (tid & 31) * 4;
            float4 fv = *(const float4*)(Fbase + (size_t)fr * FF + c + cc);
            Fs[fr][cc + 0] = fv.x; Fs[fr][cc + 1] = fv.y;
            Fs[fr][cc + 2] = fv.z; Fs[fr][cc + 3] = fv.w;
        }
        if (tid < 32) *(float4*)(&ws[tid * 4]) = *(const float4*)(wm2 + c + tid * 4);
        {
            int tr = tid >> 2, tcc0 = (tid & 3) * 32;
#pragma unroll
            for (int i = 0; i < 8; i++) {
                int cc = tcc0 + i * 4;
                float4 tv = *(const float4*)(Tbase + (size_t)tr * FF + c + cc);
                float4 bb = *(const float4*)(bm1 + c + cc);
                Ts[tr][cc + 0] = tv.x + bb.x;
                Ts[tr][cc + 1] = tv.y + bb.y;
                Ts[tr][cc + 2] = tv.z + bb.z;
                Ts[tr][cc + 3] = tv.w + bb.w;
            }
        }
        __syncthreads();

#pragma unroll 4
        for (int hh = 0; hh < PCH; hh++) {
            float fv = Fs[f][hh];
            float w = ws[hh];
            float a0 = fv + Ts[t0][hh];
            float a1 = fv + Ts[t0 + 1][hh];
            acc0  = fmaf(gelu_exact(a0), w, acc0);
            acc1v = fmaf(gelu_exact(a1), w, acc1v);
        }
        __syncthreads();
    }

    const float bm2s = bm2v[0];
    const int fg = ft * 8 + f;
    float* orow = out + ((size_t)b * S + fg) * S;
    orow[t0]     = acc0 + bm2s;
    orow[t0 + 1] = acc1v + bm2s;
}

// ---------------------------------------------------------------------------
// Launcher
// ---------------------------------------------------------------------------
extern "C" void kernel_launch(void* const* d_in, const int* in_sizes, int n_in,
                              void* d_out, int out_size)
{
    const float* emb   = (const float*)d_in[0];
    const float* Wqkv  = (const float*)d_in[1];
    const float* bqkv  = (const float*)d_in[2];
    const float* Wo    = (const float*)d_in[3];
    const float* bo    = (const float*)d_in[4];
    const float* ln1_g = (const float*)d_in[5];
    const float* ln1_b = (const float*)d_in[6];
    const float* ln2_g = (const float*)d_in[7];
    const float* ln2_b = (const float*)d_in[8];
    const float* W1    = (const float*)d_in[9];
    const float* b1    = (const float*)d_in[10];
    const float* W2    = (const float*)d_in[11];
    const float* b2    = (const float*)d_in[12];
    const float* Wm1   = (const float*)d_in[13];
    const float* bm1   = (const float*)d_in[14];
    const float* Wm2   = (const float*)d_in[15];
    const float* bm2   = (const float*)d_in[16];
    float* out = (float*)d_out;

    float *x, *qkvb, *ao, *tmp, *hb, *fb, *tb;
    cudaGetSymbolAddress((void**)&x, g_x);
    cudaGetSymbolAddress((void**)&qkvb, g_qkv);
    cudaGetSymbolAddress((void**)&ao, g_ao);
    cudaGetSymbolAddress((void**)&tmp, g_tmp);
    cudaGetSymbolAddress((void**)&hb, g_h);
    cudaGetSymbolAddress((void**)&fb, g_f);
    cudaGetSymbolAddress((void**)&tb, g_t);

    int8_t *x1, *x2, *ao1, *ao2, *h1, *h2;
    int8_t *wq1, *wq2, *wo1, *wo2, *w11, *w12, *w21, *w22, *mf1, *mf2, *mt1, *mt2;
    float *sx, *sao, *sh, *swq, *swo, *sw1, *sw2, *smf, *smt;
    cudaGetSymbolAddress((void**)&x1, q_x1);   cudaGetSymbolAddress((void**)&x2, q_x2);
    cudaGetSymbolAddress((void**)&ao1, q_ao1); cudaGetSymbolAddress((void**)&ao2, q_ao2);
    cudaGetSymbolAddress((void**)&h1, q_h1);   cudaGetSymbolAddress((void**)&h2, q_h2);
    cudaGetSymbolAddress((void**)&wq1, q_wqkv1); cudaGetSymbolAddress((void**)&wq2, q_wqkv2);
    cudaGetSymbolAddress((void**)&wo1, q_wo1); cudaGetSymbolAddress((void**)&wo2, q_wo2);
    cudaGetSymbolAddress((void**)&w11, q_w11); cudaGetSymbolAddress((void**)&w12, q_w12);
    cudaGetSymbolAddress((void**)&w21, q_w21); cudaGetSymbolAddress((void**)&w22, q_w22);
    cudaGetSymbolAddress((void**)&mf1, q_wm1f1); cudaGetSymbolAddress((void**)&mf2, q_wm1f2);
    cudaGetSymbolAddress((void**)&mt1, q_wm1t1); cudaGetSymbolAddress((void**)&mt2, q_wm1t2);
    cudaGetSymbolAddress((void**)&sx, s_x);    cudaGetSymbolAddress((void**)&sao, s_ao);
    cudaGetSymbolAddress((void**)&sh, s_h);    cudaGetSymbolAddress((void**)&swq, s_wqkv);
    cudaGetSymbolAddress((void**)&swo, s_wo);  cudaGetSymbolAddress((void**)&sw1, s_w1);
    cudaGetSymbolAddress((void**)&sw2, s_w2);  cudaGetSymbolAddress((void**)&smf, s_wm1f);
    cudaGetSymbolAddress((void**)&smt, s_wm1t);

    cudaFuncSetAttribute(ig_gemm<0>, cudaFuncAttributeMaxDynamicSharedMemorySize, IG_SMEM);
    cudaFuncSetAttribute(ig_gemm<1>, cudaFuncAttributeMaxDynamicSharedMemorySize, IG_SMEM);

    cudaMemcpyAsync(x, emb, (size_t)M_TOT * D * sizeof(float),
                    cudaMemcpyDeviceToDevice);

    quant_rows<4><<<LAYERS * 3 * D, 128>>>(Wqkv, D, wq1, wq2, swq);
    quant_rows<4><<<LAYERS * D, 128>>>(Wo, D, wo1, wo2, swo);
    quant_rows<4><<<LAYERS * FF, 128>>>(W1, D, w11, w12, sw1);
    quant_rows<8><<<LAYERS * D, 128>>>(W2, FF, w21, w22, sw2);
    quant_rows<4><<<FF, 128>>>(Wm1, 2 * D, mf1, mf2, smf);
    quant_rows<4><<<FF, 128>>>(Wm1 + D, 2 * D, mt1, mt2, smt);
    quant_rows<4><<<M_TOT, 128>>>(emb, D, x1, x2, sx);

    const dim3 gQKV(3 * D / 64, M_TOT / 128);   // (24, 32)
    const dim3 gD  (D / 64,     M_TOT / 128);   // (8, 32)
    const dim3 gFF (FF / 64,    M_TOT / 128);   // (16, 32)

    for (int l = 0; l < LAYERS; l++) {
        ig_gemm<0><<<gQKV, 256, IG_SMEM>>>(
            x1, x2, sx, D,
            wq1 + (size_t)l * 3 * D * D, wq2 + (size_t)l * 3 * D * D,
            swq + (size_t)l * 3 * D, D,
            bqkv + (size_t)l * 3 * D, qkvb, 3 * D, D);
        attn_kernel<<<B * H, 256>>>(qkvb, ao);
        quant_rows<4><<<M_TOT, 128>>>(ao, D, ao1, ao2, sao);
        ig_gemm<0><<<gD, 256, IG_SMEM>>>(
            ao1, ao2, sao, D,
            wo1 + (size_t)l * D * D, wo2 + (size_t)l * D * D,
            swo + (size_t)l * D, D,
            bo + (size_t)l * D, tmp, D, D);
        add_ln_kernel<<<M_TOT, 128>>>(x, tmp, ln1_g + (size_t)l * D,
                                      ln1_b + (size_t)l * D, x1, x2, sx);
        ig_gemm<1><<<gFF, 256, IG_SMEM>>>(
            x1, x2, sx, D,
            w11 + (size_t)l * FF * D, w12 + (size_t)l * FF * D,
            sw1 + (size_t)l * FF, D,
            b1 + (size_t)l * FF, hb, FF, D);
        quant_rows<8><<<M_TOT, 128>>>(hb, FF, h1, h2, sh);
        ig_gemm<0><<<gD, 256, IG_SMEM>>>(
            h1, h2, sh, FF,
            w21 + (size_t)l * D * FF, w22 + (size_t)l * D * FF,
            sw2 + (size_t)l * D, FF,
            b2 + (size_t)l * D, tmp, D, FF);
        add_ln_kernel<<<M_TOT, 128>>>(x, tmp, ln2_g + (size_t)l * D,
                                      ln2_b + (size_t)l * D, x1, x2, sx);
    }

    ig_gemm<0><<<gFF, 256, IG_SMEM>>>(
        x1, x2, sx, D, mf1, mf2, smf, D, nullptr, fb, FF, D);
    ig_gemm<0><<<gFF, 256, IG_SMEM>>>(
        x1, x2, sx, D, mt1, mt2, smt, D, nullptr, tb, FF, D);
    pairwise_kernel<<<B * 8, 256>>>(fb, tb, bm1, Wm2, bm2, out);
}